// round 8
// baseline (speedup 1.0000x reference)
#include <cuda_runtime.h>
#include <cuda_bf16.h>
#include <math.h>
#include <float.h>
#include <stdint.h>

#define NN   8192
#define FIN  256
#define HIDD 256
#define NE   131072
#define KT   17
#define NCAND 32
#define NCLS 10
#define NSEL 4096
#define EPSF 1e-8f

__device__ __align__(16) float d_fea[NN * FIN];
__device__ float d_dinv[NN];
__device__ int   d_cnt_e[NN];          // self-clean in k_scan
__device__ int   d_rptr[NN + 1];
__device__ int   d_cur[NN];
__device__ int   d_csrc[NE];
__device__ float d_cw[NE];
__device__ __align__(16) float d_hn[NN * 512];
__device__ __align__(16) __nv_bfloat16 d_hb[NN * 512];
__device__ __nv_bfloat16 d_simh[(size_t)NN * NN];
__device__ int   d_tidx[NN * KT];
__device__ float d_tval[NN * KT];
__device__ int   d_kcnt[NN];           // self-clean in k_kscan
__device__ int   d_kptr[NN + 1];
__device__ int   d_kcur[NN];
__device__ unsigned char d_kmut[NN * KT];
__device__ int   d_kidx[NN * KT * 2];
__device__ float d_kval[NN * KT * 2];
__device__ __align__(16) float d_xw[NN * HIDD];
__device__ __align__(16) float d_h1[NN * HIDD];
__device__ __align__(16) float d_hw[NN * HIDD];
__device__ __align__(16) float d_emb[NN * HIDD];
__device__ __align__(16) float d_sums[NCLS * HIDD]; // self-clean in k_proto
__device__ float d_cnt[NCLS];                       // self-clean in k_proto
__device__ float d_pn[NCLS * HIDD];

__device__ __forceinline__ float warp_sum(float v) {
#pragma unroll
    for (int o = 16; o > 0; o >>= 1) v += __shfl_xor_sync(0xffffffffu, v, o);
    return v;
}
__device__ __forceinline__ void red4(float4* addr, float a, float b, float c, float d) {
    asm volatile("red.global.add.v4.f32 [%0], {%1,%2,%3,%4};"
                 :: "l"(addr), "f"(a), "f"(b), "f"(c), "f"(d) : "memory");
}
__device__ __forceinline__ void fma4(float4& a, float w, const float4 v) {
    a.x += w * v.x; a.y += w * v.y; a.z += w * v.z; a.w += w * v.w;
}
__device__ __forceinline__ uint2 pack_bf16x4(float4 v) {
    __nv_bfloat162 lo = __floats2bfloat162_rn(v.x, v.y);
    __nv_bfloat162 hi = __floats2bfloat162_rn(v.z, v.w);
    uint2 r;
    r.x = *reinterpret_cast<uint32_t*>(&lo);
    r.y = *reinterpret_cast<uint32_t*>(&hi);
    return r;
}

// -------- launch 1: fea = elu(...) + degree count --------
__global__ void k_fea(const float* __restrict__ x, const float* __restrict__ cw,
                      const float* __restrict__ ps, const float* __restrict__ st,
                      const int* __restrict__ dst) {
    int idx = blockIdx.x * 256 + threadIdx.x;
    int f = idx & (FIN - 1);
    float z = x[idx] * (cw[0] * ps[f] + cw[1] * st[f]);
    d_fea[idx] = z > 0.f ? z : expm1f(z);
    if (idx < NE) atomicAdd(&d_cnt_e[dst[idx]], 1);
}
// -------- launch 2: scan (+self-clean counts) --------
__global__ void k_scan() {
    __shared__ int bs[256];
    int t = threadIdx.x;
    int loc[32]; int s = 0;
#pragma unroll
    for (int q = 0; q < 32; q++) {
        loc[q] = d_cnt_e[t * 32 + q];
        d_cnt_e[t * 32 + q] = 0;
        s += loc[q];
    }
    bs[t] = s; __syncthreads();
    for (int off = 1; off < 256; off <<= 1) {
        int v = (t >= off) ? bs[t - off] : 0;
        __syncthreads();
        bs[t] += v;
        __syncthreads();
    }
    int run = bs[t] - s;
#pragma unroll
    for (int q = 0; q < 32; q++) {
        int i = t * 32 + q;
        d_rptr[i] = run; d_cur[i] = run;
        d_dinv[i] = rsqrtf((float)(loc[q] + 1));
        run += loc[q];
    }
    if (t == 255) d_rptr[NN] = run;
}
// -------- launch 3: CSR fill --------
__global__ void k_fill(const int* __restrict__ src, const int* __restrict__ dst) {
    int e = blockIdx.x * 256 + threadIdx.x;
    if (e >= NE) return;
    int s = src[e], d = dst[e];
    int pos = atomicAdd(&d_cur[d], 1);
    d_csrc[pos] = s;
    d_cw[pos] = d_dinv[s] * d_dinv[d];
}
// -------- launch 4: fused aggregate-gather + h-normalize + bf16 --------
__global__ void k_agg_h(const float* __restrict__ bal) {
    int gw = (blockIdx.x * 256 + threadIdx.x) >> 5, lane = threadIdx.x & 31;
    if (gw >= NN) return;
    float di = d_dinv[gw];
    const float4* fr = (const float4*)(d_fea + (size_t)gw * 256);
    float4 f0 = fr[lane], f1 = fr[lane + 32];
    float sc = di * di;
    float4 a0 = make_float4(sc*f0.x, sc*f0.y, sc*f0.z, sc*f0.w);
    float4 a1 = make_float4(sc*f1.x, sc*f1.y, sc*f1.z, sc*f1.w);
    int b = d_rptr[gw], e = d_rptr[gw + 1];
    int p = b;
    for (; p + 1 < e; p += 2) {
        float w0 = d_cw[p], w1 = d_cw[p + 1];
        const float4* s0 = (const float4*)(d_fea + (size_t)d_csrc[p] * 256);
        const float4* s1 = (const float4*)(d_fea + (size_t)d_csrc[p + 1] * 256);
        float4 v00 = s0[lane], v01 = s0[lane + 32];
        float4 v10 = s1[lane], v11 = s1[lane + 32];
        fma4(a0, w0, v00); fma4(a1, w0, v01);
        fma4(a0, w1, v10); fma4(a1, w1, v11);
    }
    if (p < e) {
        float wv = d_cw[p];
        const float4* fs = (const float4*)(d_fea + (size_t)d_csrc[p] * 256);
        fma4(a0, wv, fs[lane]); fma4(a1, wv, fs[lane + 32]);
    }
    const float4* bb = (const float4*)bal;
    float4 bA = bb[lane], bB = bb[lane + 32], bC = bb[64 + lane], bD = bb[96 + lane];
    float4 hA = make_float4(f0.x*bA.x, f0.y*bA.y, f0.z*bA.z, f0.w*bA.w);
    float4 hB = make_float4(f1.x*bB.x, f1.y*bB.y, f1.z*bB.z, f1.w*bB.w);
    float4 hC = make_float4(a0.x*bC.x, a0.y*bC.y, a0.z*bC.z, a0.w*bC.w);
    float4 hD = make_float4(a1.x*bD.x, a1.y*bD.y, a1.z*bD.z, a1.w*bD.w);
    float ss = hA.x*hA.x+hA.y*hA.y+hA.z*hA.z+hA.w*hA.w
             + hB.x*hB.x+hB.y*hB.y+hB.z*hB.z+hB.w*hB.w
             + hC.x*hC.x+hC.y*hC.y+hC.z*hC.z+hC.w*hC.w
             + hD.x*hD.x+hD.y*hD.y+hD.z*hD.z+hD.w*hD.w;
    ss = warp_sum(ss);
    float rn = 1.f / (sqrtf(ss) + EPSF);
    hA.x*=rn; hA.y*=rn; hA.z*=rn; hA.w*=rn;
    hB.x*=rn; hB.y*=rn; hB.z*=rn; hB.w*=rn;
    hC.x*=rn; hC.y*=rn; hC.z*=rn; hC.w*=rn;
    hD.x*=rn; hD.y*=rn; hD.z*=rn; hD.w*=rn;
    float4* hr = (float4*)(d_hn + (size_t)gw * 512);
    hr[lane] = hA; hr[lane + 32] = hB; hr[64 + lane] = hC; hr[96 + lane] = hD;
    uint2* hb = (uint2*)(d_hb + (size_t)gw * 512);
    hb[lane] = pack_bf16x4(hA); hb[lane + 32] = pack_bf16x4(hB);
    hb[64 + lane] = pack_bf16x4(hC); hb[96 + lane] = pack_bf16x4(hD);
}

// ======== sims = hb @ hb^T via mma.sync, bf16 output ========
__device__ __forceinline__ uint32_t smem_u32(const void* p) {
    uint32_t a;
    asm("{ .reg .u64 t; cvta.to.shared.u64 t, %1; cvt.u32.u64 %0, t; }" : "=r"(a) : "l"(p));
    return a;
}
__device__ __forceinline__ void ldsm4(uint32_t* r, uint32_t addr) {
    asm volatile("ldmatrix.sync.aligned.m8n8.x4.shared.b16 {%0,%1,%2,%3}, [%4];"
                 : "=r"(r[0]), "=r"(r[1]), "=r"(r[2]), "=r"(r[3]) : "r"(addr));
}
__device__ __forceinline__ void mma16816(float* c, const uint32_t* a, uint32_t b0, uint32_t b1) {
    asm volatile("mma.sync.aligned.m16n8k16.row.col.f32.bf16.bf16.f32 "
                 "{%0,%1,%2,%3}, {%4,%5,%6,%7}, {%8,%9}, {%0,%1,%2,%3};"
                 : "+f"(c[0]), "+f"(c[1]), "+f"(c[2]), "+f"(c[3])
                 : "r"(a[0]), "r"(a[1]), "r"(a[2]), "r"(a[3]), "r"(b0), "r"(b1));
}
__device__ __forceinline__ void sims_load(uint32_t sbase, const __nv_bfloat16* Ag,
                                          const __nv_bfloat16* Bg, int c, int tid) {
#pragma unroll
    for (int h = 0; h < 2; h++) {
        const __nv_bfloat16* G = h ? Bg : Ag;
        uint32_t base = sbase + (uint32_t)h * 16384;
#pragma unroll
        for (int q = 0; q < 4; q++) {
            int seg = tid + 256 * q;
            int r = seg >> 3, s8 = seg & 7;
            uint32_t dst = base + r * 128 + ((s8 ^ (r & 7)) << 4);
            const char* src = (const char*)(G + (size_t)r * 512 + c * 64 + s8 * 8);
            asm volatile("cp.async.cg.shared.global [%0], [%1], 16;"
                         :: "r"(dst), "l"(src) : "memory");
        }
    }
    asm volatile("cp.async.commit_group;" ::: "memory");
}
#define SIMS_SMEM 66048

__global__ void __launch_bounds__(256, 2) k_mma_sims() {
    int bi = blockIdx.y, bj = blockIdx.x;
    if (bj < bi) return;
    extern __shared__ char smem[];
    uint32_t sb = smem_u32(smem);
    int tid = threadIdx.x;
    int lane = tid & 31, w = tid >> 5;
    int wm = (w & 1) * 64, wn = (w >> 1) * 32;

    const __nv_bfloat16* Ag = d_hb + (size_t)bi * 128 * 512;
    const __nv_bfloat16* Bg = d_hb + (size_t)bj * 128 * 512;

    float acc[4][4][4];
#pragma unroll
    for (int mt = 0; mt < 4; mt++)
#pragma unroll
        for (int nt = 0; nt < 4; nt++)
#pragma unroll
            for (int e = 0; e < 4; e++) acc[mt][nt][e] = 0.f;

    sims_load(sb, Ag, Bg, 0, tid);
    int lr = lane & 15, lks = lane >> 4;
    for (int c = 0; c < 8; c++) {
        if (c < 7) sims_load(sb + ((c + 1) & 1) * 32768, Ag, Bg, c + 1, tid);
        if (c < 7) asm volatile("cp.async.wait_group 1;" ::: "memory");
        else       asm volatile("cp.async.wait_group 0;" ::: "memory");
        __syncthreads();
        uint32_t aB = sb + (c & 1) * 32768, bB = aB + 16384;
#pragma unroll
        for (int ks = 0; ks < 4; ks++) {
            int segk = ks * 2 + lks;
            uint32_t a[4][4], b[2][4];
#pragma unroll
            for (int mt = 0; mt < 4; mt++) {
                int r = wm + mt * 16 + lr;
                ldsm4(a[mt], aB + r * 128 + ((segk ^ (r & 7)) << 4));
            }
#pragma unroll
            for (int bt = 0; bt < 2; bt++) {
                int r = wn + bt * 16 + lr;
                ldsm4(b[bt], bB + r * 128 + ((segk ^ (r & 7)) << 4));
            }
#pragma unroll
            for (int mt = 0; mt < 4; mt++)
#pragma unroll
                for (int nt = 0; nt < 4; nt++)
                    mma16816(acc[mt][nt], a[mt], b[nt >> 1][nt & 1], b[nt >> 1][(nt & 1) + 2]);
        }
        __syncthreads();
    }
    float* sf = (float*)smem;
    int g = lane >> 2, tq = lane & 3;
#pragma unroll
    for (int mt = 0; mt < 4; mt++)
#pragma unroll
        for (int nt = 0; nt < 4; nt++) {
            int r0 = wm + mt * 16 + g, c0 = wn + nt * 8 + tq * 2;
            sf[r0 * 129 + c0]           = acc[mt][nt][0];
            sf[r0 * 129 + c0 + 1]       = acc[mt][nt][1];
            sf[(r0 + 8) * 129 + c0]     = acc[mt][nt][2];
            sf[(r0 + 8) * 129 + c0 + 1] = acc[mt][nt][3];
        }
    __syncthreads();
    size_t gi0 = (size_t)bi * 128, gj0 = (size_t)bj * 128;
    if (bi != bj) {
        for (int it = tid; it < 128 * 64; it += 256) {
            int r = it >> 6, c2 = (it & 63) * 2;
            __nv_bfloat162 p = __floats2bfloat162_rn(sf[r * 129 + c2], sf[r * 129 + c2 + 1]);
            *(__nv_bfloat162*)&d_simh[(gi0 + r) * NN + gj0 + c2] = p;
        }
        for (int it = tid; it < 128 * 64; it += 256) {
            int j = it >> 6, i2 = (it & 63) * 2;
            __nv_bfloat162 p = __floats2bfloat162_rn(sf[i2 * 129 + j], sf[(i2 + 1) * 129 + j]);
            *(__nv_bfloat162*)&d_simh[(gj0 + j) * NN + gi0 + i2] = p;
        }
    } else {
        for (int it = tid; it < 128 * 64; it += 256) {
            int r = it >> 6, c2 = (it & 63) * 2;
            float v0 = (c2 >= r)     ? sf[r * 129 + c2]     : sf[c2 * 129 + r];
            float v1 = (c2 + 1 >= r) ? sf[r * 129 + c2 + 1] : sf[(c2 + 1) * 129 + r];
            __nv_bfloat162 p = __floats2bfloat162_rn(v0, v1);
            *(__nv_bfloat162*)&d_simh[(gi0 + r) * NN + gj0 + c2] = p;
        }
    }
}

// -------- top-32 warp-parallel two-stage select + exact fp32 rescore -> top-17 --------
__global__ void k_topk(const float* __restrict__ alphap) {
    int row = blockIdx.x, t = threadIdx.x;
    int w = t >> 5, lane = t & 31;
    const __nv_bfloat16* srow = d_simh + (size_t)row * NN;
    // warp w owns columns [w*1024, w*1024+1024); lane's col = w*1024 + q*32 + lane
    float v[32];
#pragma unroll
    for (int q = 0; q < 32; q++)
        v[q] = __bfloat162float(srow[w * 1024 + q * 32 + lane]);
    unsigned rem = 0;
    float m = -FLT_MAX; int a = 0;
#pragma unroll
    for (int q = 0; q < 32; q++) if (v[q] > m) { m = v[q]; a = q; }
    __shared__ float cval[256];
    __shared__ int   cidx[256];
    // stage 1: each warp extracts its local top-32 (no block syncs)
    for (int it = 0; it < 32; it++) {
        float mv = m;
        int mi = w * 1024 + a * 32 + lane;
#pragma unroll
        for (int o = 16; o > 0; o >>= 1) {
            float ov = __shfl_xor_sync(0xffffffffu, mv, o);
            int   oi = __shfl_xor_sync(0xffffffffu, mi, o);
            if (ov > mv || (ov == mv && oi < mi)) { mv = ov; mi = oi; }
        }
        if (lane == 0) { cval[w * 32 + it] = mv; cidx[w * 32 + it] = mi; }
        if ((mi & 31) == lane) {               // owner invalidates + rescans
            rem |= 1u << ((mi >> 5) & 31);
            m = -FLT_MAX; a = 0;
#pragma unroll
            for (int q = 0; q < 32; q++) {
                float vq = ((rem >> q) & 1u) ? -FLT_MAX : v[q];
                if (vq > m) { m = vq; a = q; }
            }
        }
    }
    __syncthreads();
    // stage 2: warp 0 merges 256 candidates -> global top-32
    __shared__ int   cand[NCAND];
    __shared__ float cex[NCAND];
    if (w == 0) {
        float lv[8]; int li[8];
#pragma unroll
        for (int q = 0; q < 8; q++) { lv[q] = cval[q * 32 + lane]; li[q] = cidx[q * 32 + lane]; }
        unsigned rem2 = 0;
        float m2 = -FLT_MAX; int a2 = 0;
#pragma unroll
        for (int q = 0; q < 8; q++)
            if (lv[q] > m2 || (lv[q] == m2 && li[q] < li[a2])) { m2 = lv[q]; a2 = q; }
        for (int it = 0; it < NCAND; it++) {
            float mv = m2; int mi = li[a2];
#pragma unroll
            for (int o = 16; o > 0; o >>= 1) {
                float ov = __shfl_xor_sync(0xffffffffu, mv, o);
                int   oi = __shfl_xor_sync(0xffffffffu, mi, o);
                if (ov > mv || (ov == mv && oi < mi)) { mv = ov; mi = oi; }
            }
            if (lane == 0) cand[it] = mi;
            if (li[a2] == mi && m2 == mv) {    // unique owner (indices distinct)
                rem2 |= 1u << a2;
                m2 = -FLT_MAX; a2 = 0;
#pragma unroll
                for (int q = 0; q < 8; q++) {
                    float vq = ((rem2 >> q) & 1u) ? -FLT_MAX : lv[q];
                    if (vq > m2 || (vq == m2 && li[q] < li[a2])) { m2 = vq; a2 = q; }
                }
            }
        }
    }
    __syncthreads();
    // stage 3: exact fp32 rescore (warp w -> candidates 4w..4w+3)
    const float* hr = d_hn + (size_t)row * 512;
#pragma unroll
    for (int c = w * 4; c < w * 4 + 4; c++) {
        const float* hj = d_hn + (size_t)cand[c] * 512;
        float s = 0.f;
#pragma unroll
        for (int e = 0; e < 16; e++) s += hr[lane + e * 32] * hj[lane + e * 32];
        s = warp_sum(s);
        if (lane == 0) cex[c] = s;
    }
    __syncthreads();
    if (t == 0) {
        float onema = 1.f - *alphap;
        unsigned used = 0;
        for (int it = 0; it < KT; it++) {
            float bv = -FLT_MAX; int bc = -1;
            for (int c = 0; c < NCAND; c++) {
                if ((used >> c) & 1u) continue;
                if (bc < 0 || cex[c] > bv || (cex[c] == bv && cand[c] < cand[bc]))
                    { bv = cex[c]; bc = c; }
            }
            used |= 1u << bc;
            d_tidx[row * KT + it] = cand[bc];
            d_tval[row * KT + it] = onema * fmaxf(bv, 0.f);
        }
    }
}

// -------- kNN symmetric CSR build --------
__global__ void k_kcount() {
    int w = (blockIdx.x * 256 + threadIdx.x) >> 5, lane = threadIdx.x & 31;
    if (w >= NN * KT) return;
    int i = w / KT, j = d_tidx[w];
    int cand = (lane < KT) ? d_tidx[j * KT + lane] : -1;
    unsigned f = __ballot_sync(0xffffffffu, cand == i);
    if (lane == 0) {
        atomicAdd(&d_kcnt[i], 1);
        d_kmut[w] = (f != 0);
        if (!f) atomicAdd(&d_kcnt[j], 1);
    }
}
__global__ void k_kscan() {
    __shared__ int bs[256];
    int t = threadIdx.x;
    int loc[32]; int s = 0;
#pragma unroll
    for (int q = 0; q < 32; q++) {
        loc[q] = d_kcnt[t * 32 + q];
        d_kcnt[t * 32 + q] = 0;
        s += loc[q];
    }
    bs[t] = s; __syncthreads();
    for (int off = 1; off < 256; off <<= 1) {
        int v = (t >= off) ? bs[t - off] : 0;
        __syncthreads();
        bs[t] += v;
        __syncthreads();
    }
    int run = bs[t] - s;
#pragma unroll
    for (int q = 0; q < 32; q++) {
        int i = t * 32 + q;
        d_kptr[i] = run; d_kcur[i] = run;
        run += loc[q];
    }
    if (t == 255) d_kptr[NN] = run;
}
__global__ void k_kfill() {
    int w = blockIdx.x * 256 + threadIdx.x;
    if (w >= NN * KT) return;
    int i = w / KT, j = d_tidx[w];
    float v = d_tval[w];
    int pos = atomicAdd(&d_kcur[i], 1);
    d_kidx[pos] = j; d_kval[pos] = v;
    if (!d_kmut[w]) {
        int pos2 = atomicAdd(&d_kcur[j], 1);
        d_kidx[pos2] = i; d_kval[pos2] = v;
    }
}

// -------- dense [8192,256]@[256,256] fp32 GEMM --------
template <int L>
__global__ void k_sgemm_nn(const float* __restrict__ W) {
    const float* A = (L == 0) ? d_fea : d_h1;
    float* C = (L == 0) ? d_xw : d_hw;
    int bm = blockIdx.y, bn = blockIdx.x;
    __shared__ float As[16][132];
    __shared__ float Bs[16][132];
    int tid = threadIdx.x, tm = tid >> 4, tn = tid & 15;
    float acc[8][8];
#pragma unroll
    for (int u = 0; u < 8; u++)
#pragma unroll
        for (int v = 0; v < 8; v++) acc[u][v] = 0.f;
    int r = tid >> 1, kc = (tid & 1) * 8;
    int kb = tid >> 4, nb = (tid & 15) * 8;
    for (int k0 = 0; k0 < 256; k0 += 16) {
        float4 a0 = *(const float4*)&A[(size_t)(bm*128+r)*256 + k0 + kc];
        float4 a1 = *(const float4*)&A[(size_t)(bm*128+r)*256 + k0 + kc + 4];
        float4 b0 = *(const float4*)&W[(size_t)(k0+kb)*256 + bn*128 + nb];
        float4 b1 = *(const float4*)&W[(size_t)(k0+kb)*256 + bn*128 + nb + 4];
        __syncthreads();
        As[kc+0][r]=a0.x; As[kc+1][r]=a0.y; As[kc+2][r]=a0.z; As[kc+3][r]=a0.w;
        As[kc+4][r]=a1.x; As[kc+5][r]=a1.y; As[kc+6][r]=a1.z; As[kc+7][r]=a1.w;
        *(float4*)&Bs[kb][nb] = b0;
        *(float4*)&Bs[kb][nb+4] = b1;
        __syncthreads();
#pragma unroll
        for (int kk = 0; kk < 16; kk++) {
            float av[8], bv[8];
#pragma unroll
            for (int u = 0; u < 8; u++) { av[u]=As[kk][tm*8+u]; bv[u]=Bs[kk][tn*8+u]; }
#pragma unroll
            for (int u = 0; u < 8; u++)
#pragma unroll
                for (int vv = 0; vv < 8; vv++) acc[u][vv] += av[u]*bv[vv];
        }
    }
#pragma unroll
    for (int u = 0; u < 8; u++) {
        float* crow = &C[(size_t)(bm*128+tm*8+u)*256 + bn*128 + tn*8];
        *(float4*)crow     = make_float4(acc[u][0],acc[u][1],acc[u][2],acc[u][3]);
        *(float4*)(crow+4) = make_float4(acc[u][4],acc[u][5],acc[u][6],acc[u][7]);
    }
}

// -------- gather-based A_tot @ X --------
template <int L>
__global__ void k_spmm_gather(const float* __restrict__ alphap) {
    int gw = (blockIdx.x * 256 + threadIdx.x) >> 5, lane = threadIdx.x & 31;
    if (gw >= NN) return;
    const float* X = (L == 0) ? d_xw : d_hw;
    float* out = (L == 0) ? d_h1 : d_emb;
    float alpha = *alphap;
    float di = d_dinv[gw];
    const float4* xr = (const float4*)(X + (size_t)gw * 256);
    float4 x0 = xr[lane], x1 = xr[lane + 32];
    float sc = di * di;
    float4 a0 = make_float4(sc*x0.x, sc*x0.y, sc*x0.z, sc*x0.w);
    float4 a1 = make_float4(sc*x1.x, sc*x1.y, sc*x1.z, sc*x1.w);
    int b = d_rptr[gw], e = d_rptr[gw + 1];
    int p = b;
    for (; p + 1 < e; p += 2) {
        float w0 = d_cw[p], w1 = d_cw[p + 1];
        const float4* s0 = (const float4*)(X + (size_t)d_csrc[p] * 256);
        const float4* s1 = (const float4*)(X + (size_t)d_csrc[p + 1] * 256);
        float4 v00 = s0[lane], v01 = s0[lane + 32];
        float4 v10 = s1[lane], v11 = s1[lane + 32];
        fma4(a0, w0, v00); fma4(a1, w0, v01);
        fma4(a0, w1, v10); fma4(a1, w1, v11);
    }
    if (p < e) {
        float wv = d_cw[p];
        const float4* xs = (const float4*)(X + (size_t)d_csrc[p] * 256);
        fma4(a0, wv, xs[lane]); fma4(a1, wv, xs[lane + 32]);
    }
    a0.x*=alpha; a0.y*=alpha; a0.z*=alpha; a0.w*=alpha;
    a1.x*=alpha; a1.y*=alpha; a1.z*=alpha; a1.w*=alpha;
    int kb = d_kptr[gw], ke = d_kptr[gw + 1];
    p = kb;
    for (; p + 1 < ke; p += 2) {
        float w0 = d_kval[p], w1 = d_kval[p + 1];
        const float4* s0 = (const float4*)(X + (size_t)d_kidx[p] * 256);
        const float4* s1 = (const float4*)(X + (size_t)d_kidx[p + 1] * 256);
        float4 v00 = s0[lane], v01 = s0[lane + 32];
        float4 v10 = s1[lane], v11 = s1[lane + 32];
        fma4(a0, w0, v00); fma4(a1, w0, v01);
        fma4(a0, w1, v10); fma4(a1, w1, v11);
    }
    if (p < ke) {
        float v = d_kval[p];
        const float4* xs = (const float4*)(X + (size_t)d_kidx[p] * 256);
        fma4(a0, v, xs[lane]); fma4(a1, v, xs[lane + 32]);
    }
    if (L == 0) {
        a0.x=fmaxf(a0.x,0.f); a0.y=fmaxf(a0.y,0.f); a0.z=fmaxf(a0.z,0.f); a0.w=fmaxf(a0.w,0.f);
        a1.x=fmaxf(a1.x,0.f); a1.y=fmaxf(a1.y,0.f); a1.z=fmaxf(a1.z,0.f); a1.w=fmaxf(a1.w,0.f);
    }
    float4* orow = (float4*)(out + (size_t)gw * 256);
    orow[lane] = a0; orow[lane + 32] = a1;
}

// -------- classification --------
__global__ void k_cls_scatter(const int* __restrict__ labels, const int* __restrict__ nidx) {
    int w = (blockIdx.x*256+threadIdx.x) >> 5, lane = threadIdx.x & 31;
    if (w >= NSEL) return;
    int lbl = labels[w];
    const float4* er = (const float4*)(d_emb + (size_t)nidx[w]*HIDD);
    float4* sr = (float4*)(d_sums + lbl*HIDD);
#pragma unroll
    for (int q = 0; q < 2; q++) {
        int f = lane + 32*q; float4 v = er[f];
        red4(&sr[f], v.x, v.y, v.z, v.w);
    }
    if (lane == 0) atomicAdd(&d_cnt[lbl], 1.f);
}
__global__ void k_proto() {
    int c = blockIdx.x, t = threadIdx.x;
    float cnt = d_cnt[c];
    float sm = d_sums[c*HIDD+t];
    float p = sm / fmaxf(cnt, 1.f);
    __shared__ float red[256];
    red[t] = p*p;
    __syncthreads();
    for (int s = 128; s > 0; s >>= 1) { if (t < s) red[t] += red[t+s]; __syncthreads(); }
    d_pn[c*HIDD+t] = p / (sqrtf(red[0]) + EPSF);
    d_sums[c*HIDD+t] = 0.f;
    if (t == 0) d_cnt[c] = 0.f;
}
__global__ void k_out(const int* __restrict__ nidx, float* __restrict__ out) {
    int w = (blockIdx.x*256+threadIdx.x) >> 5, lane = threadIdx.x & 31;
    if (w >= NSEL) return;
    const float* er = d_emb + (size_t)nidx[w]*HIDD;
    float v[8]; float ss = 0.f;
#pragma unroll
    for (int q = 0; q < 8; q++) { v[q] = er[lane+32*q]; ss += v[q]*v[q]; }
    ss = warp_sum(ss);
    float rn = 1.f / (sqrtf(ss) + EPSF);
#pragma unroll
    for (int c = 0; c < NCLS; c++) {
        float dp = 0.f;
#pragma unroll
        for (int q = 0; q < 8; q++) dp += v[q] * d_pn[c*HIDD + lane + 32*q];
        dp = warp_sum(dp);
        if (lane == 0) out[w*NCLS + c] = dp * rn * 5.0f;
    }
}

extern "C" void kernel_launch(void* const* d_in, const int* in_sizes, int n_in,
                              void* d_out, int out_size) {
    const float* x   = (const float*)d_in[0];
    const float* cw  = (const float*)d_in[1];
    const float* alp = (const float*)d_in[2];
    const float* ps  = (const float*)d_in[3];
    const float* st  = (const float*)d_in[4];
    const float* bal = (const float*)d_in[5];
    const float* W1  = (const float*)d_in[6];
    const float* W2  = (const float*)d_in[7];
    const int*   ei  = (const int*)d_in[8];
    const int*   lab = (const int*)d_in[9];
    const int*   nix = (const int*)d_in[10];
    float* out = (float*)d_out;
    const int* esrc = ei;
    const int* edst = ei + NE;

    cudaFuncSetAttribute(k_mma_sims, cudaFuncAttributeMaxDynamicSharedMemorySize, SIMS_SMEM);

    k_fea<<<NN*FIN/256, 256>>>(x, cw, ps, st, edst);
    k_scan<<<1, 256>>>();
    k_fill<<<NE/256, 256>>>(esrc, edst);
    k_agg_h<<<NN/8, 256>>>(bal);
    k_mma_sims<<<dim3(64, 64), 256, SIMS_SMEM>>>();
    k_topk<<<NN, 256>>>(alp);
    k_kcount<<<NN*KT/8, 256>>>();
    k_kscan<<<1, 256>>>();
    k_kfill<<<(NN*KT+255)/256, 256>>>();

    k_sgemm_nn<0><<<dim3(2, 64), 256>>>(W1);
    k_spmm_gather<0><<<NN/8, 256>>>(alp);
    k_sgemm_nn<1><<<dim3(2, 64), 256>>>(W2);
    k_spmm_gather<1><<<NN/8, 256>>>(alp);

    k_cls_scatter<<<NSEL/8, 256>>>(lab, nix);
    k_proto<<<NCLS, 256>>>();
    k_out<<<NSEL/8, 256>>>(nix, out);
}

// round 9
// speedup vs baseline: 2.2898x; 2.2898x over previous
#include <cuda_runtime.h>
#include <cuda_bf16.h>
#include <math.h>
#include <float.h>
#include <stdint.h>

#define NN   8192
#define FIN  256
#define HIDD 256
#define NE   131072
#define KT   17
#define CANDCAP 64
#define NCLS 10
#define NSEL 4096
#define EPSF 1e-8f

__device__ __align__(16) float d_fea[NN * FIN];
__device__ float d_dinv[NN];
__device__ int   d_cnt_e[NN];          // self-clean in k_scan
__device__ int   d_rptr[NN + 1];
__device__ int   d_cur[NN];
__device__ int   d_csrc[NE];
__device__ float d_cw[NE];
__device__ __align__(16) float d_hn[NN * 512];
__device__ __align__(16) __nv_bfloat16 d_hb[NN * 512];
__device__ __nv_bfloat16 d_simh[(size_t)NN * NN];
__device__ int   d_tidx[NN * KT];
__device__ float d_tval[NN * KT];
__device__ int   d_kcnt[NN];           // self-clean in k_kscan
__device__ int   d_kptr[NN + 1];
__device__ int   d_kcur[NN];
__device__ unsigned char d_kmut[NN * KT];
__device__ int   d_kidx[NN * KT * 2];
__device__ float d_kval[NN * KT * 2];
__device__ __align__(16) float d_xw[NN * HIDD];
__device__ __align__(16) float d_h1[NN * HIDD];
__device__ __align__(16) float d_hw[NN * HIDD];
__device__ __align__(16) float d_emb[NN * HIDD];
__device__ __align__(16) float d_sums[NCLS * HIDD]; // self-clean in k_proto
__device__ float d_cnt[NCLS];                       // self-clean in k_proto
__device__ float d_pn[NCLS * HIDD];

__device__ __forceinline__ float warp_sum(float v) {
#pragma unroll
    for (int o = 16; o > 0; o >>= 1) v += __shfl_xor_sync(0xffffffffu, v, o);
    return v;
}
__device__ __forceinline__ void red4(float4* addr, float a, float b, float c, float d) {
    asm volatile("red.global.add.v4.f32 [%0], {%1,%2,%3,%4};"
                 :: "l"(addr), "f"(a), "f"(b), "f"(c), "f"(d) : "memory");
}
__device__ __forceinline__ void fma4(float4& a, float w, const float4 v) {
    a.x += w * v.x; a.y += w * v.y; a.z += w * v.z; a.w += w * v.w;
}
__device__ __forceinline__ uint2 pack_bf16x4(float4 v) {
    __nv_bfloat162 lo = __floats2bfloat162_rn(v.x, v.y);
    __nv_bfloat162 hi = __floats2bfloat162_rn(v.z, v.w);
    uint2 r;
    r.x = *reinterpret_cast<uint32_t*>(&lo);
    r.y = *reinterpret_cast<uint32_t*>(&hi);
    return r;
}
// monotone uint16 key for bf16 bits (larger value -> larger key)
__device__ __forceinline__ uint32_t bf16key(uint32_t b) {  // b: low 16 bits valid
    return (b & 0x8000u) ? (~b & 0xFFFFu) : (b | 0x8000u);
}

// -------- launch 1: fea = elu(...) + degree count --------
__global__ void k_fea(const float* __restrict__ x, const float* __restrict__ cw,
                      const float* __restrict__ ps, const float* __restrict__ st,
                      const int* __restrict__ dst) {
    int idx = blockIdx.x * 256 + threadIdx.x;
    int f = idx & (FIN - 1);
    float z = x[idx] * (cw[0] * ps[f] + cw[1] * st[f]);
    d_fea[idx] = z > 0.f ? z : expm1f(z);
    if (idx < NE) atomicAdd(&d_cnt_e[dst[idx]], 1);
}
// -------- launch 2: scan (+self-clean counts) --------
__global__ void k_scan() {
    __shared__ int bs[256];
    int t = threadIdx.x;
    int loc[32]; int s = 0;
#pragma unroll
    for (int q = 0; q < 32; q++) {
        loc[q] = d_cnt_e[t * 32 + q];
        d_cnt_e[t * 32 + q] = 0;
        s += loc[q];
    }
    bs[t] = s; __syncthreads();
    for (int off = 1; off < 256; off <<= 1) {
        int v = (t >= off) ? bs[t - off] : 0;
        __syncthreads();
        bs[t] += v;
        __syncthreads();
    }
    int run = bs[t] - s;
#pragma unroll
    for (int q = 0; q < 32; q++) {
        int i = t * 32 + q;
        d_rptr[i] = run; d_cur[i] = run;
        d_dinv[i] = rsqrtf((float)(loc[q] + 1));
        run += loc[q];
    }
    if (t == 255) d_rptr[NN] = run;
}
// -------- launch 3: CSR fill --------
__global__ void k_fill(const int* __restrict__ src, const int* __restrict__ dst) {
    int e = blockIdx.x * 256 + threadIdx.x;
    if (e >= NE) return;
    int s = src[e], d = dst[e];
    int pos = atomicAdd(&d_cur[d], 1);
    d_csrc[pos] = s;
    d_cw[pos] = d_dinv[s] * d_dinv[d];
}
// -------- launch 4: fused aggregate-gather + h-normalize + bf16 --------
__global__ void k_agg_h(const float* __restrict__ bal) {
    int gw = (blockIdx.x * 256 + threadIdx.x) >> 5, lane = threadIdx.x & 31;
    if (gw >= NN) return;
    float di = d_dinv[gw];
    const float4* fr = (const float4*)(d_fea + (size_t)gw * 256);
    float4 f0 = fr[lane], f1 = fr[lane + 32];
    float sc = di * di;
    float4 a0 = make_float4(sc*f0.x, sc*f0.y, sc*f0.z, sc*f0.w);
    float4 a1 = make_float4(sc*f1.x, sc*f1.y, sc*f1.z, sc*f1.w);
    int b = d_rptr[gw], e = d_rptr[gw + 1];
    int p = b;
    for (; p + 1 < e; p += 2) {
        float w0 = d_cw[p], w1 = d_cw[p + 1];
        const float4* s0 = (const float4*)(d_fea + (size_t)d_csrc[p] * 256);
        const float4* s1 = (const float4*)(d_fea + (size_t)d_csrc[p + 1] * 256);
        float4 v00 = s0[lane], v01 = s0[lane + 32];
        float4 v10 = s1[lane], v11 = s1[lane + 32];
        fma4(a0, w0, v00); fma4(a1, w0, v01);
        fma4(a0, w1, v10); fma4(a1, w1, v11);
    }
    if (p < e) {
        float wv = d_cw[p];
        const float4* fs = (const float4*)(d_fea + (size_t)d_csrc[p] * 256);
        fma4(a0, wv, fs[lane]); fma4(a1, wv, fs[lane + 32]);
    }
    const float4* bb = (const float4*)bal;
    float4 bA = bb[lane], bB = bb[lane + 32], bC = bb[64 + lane], bD = bb[96 + lane];
    float4 hA = make_float4(f0.x*bA.x, f0.y*bA.y, f0.z*bA.z, f0.w*bA.w);
    float4 hB = make_float4(f1.x*bB.x, f1.y*bB.y, f1.z*bB.z, f1.w*bB.w);
    float4 hC = make_float4(a0.x*bC.x, a0.y*bC.y, a0.z*bC.z, a0.w*bC.w);
    float4 hD = make_float4(a1.x*bD.x, a1.y*bD.y, a1.z*bD.z, a1.w*bD.w);
    float ss = hA.x*hA.x+hA.y*hA.y+hA.z*hA.z+hA.w*hA.w
             + hB.x*hB.x+hB.y*hB.y+hB.z*hB.z+hB.w*hB.w
             + hC.x*hC.x+hC.y*hC.y+hC.z*hC.z+hC.w*hC.w
             + hD.x*hD.x+hD.y*hD.y+hD.z*hD.z+hD.w*hD.w;
    ss = warp_sum(ss);
    float rn = 1.f / (sqrtf(ss) + EPSF);
    hA.x*=rn; hA.y*=rn; hA.z*=rn; hA.w*=rn;
    hB.x*=rn; hB.y*=rn; hB.z*=rn; hB.w*=rn;
    hC.x*=rn; hC.y*=rn; hC.z*=rn; hC.w*=rn;
    hD.x*=rn; hD.y*=rn; hD.z*=rn; hD.w*=rn;
    float4* hr = (float4*)(d_hn + (size_t)gw * 512);
    hr[lane] = hA; hr[lane + 32] = hB; hr[64 + lane] = hC; hr[96 + lane] = hD;
    uint2* hb = (uint2*)(d_hb + (size_t)gw * 512);
    hb[lane] = pack_bf16x4(hA); hb[lane + 32] = pack_bf16x4(hB);
    hb[64 + lane] = pack_bf16x4(hC); hb[96 + lane] = pack_bf16x4(hD);
}

// ======== sims = hb @ hb^T via mma.sync, bf16 output ========
__device__ __forceinline__ uint32_t smem_u32(const void* p) {
    uint32_t a;
    asm("{ .reg .u64 t; cvta.to.shared.u64 t, %1; cvt.u32.u64 %0, t; }" : "=r"(a) : "l"(p));
    return a;
}
__device__ __forceinline__ void ldsm4(uint32_t* r, uint32_t addr) {
    asm volatile("ldmatrix.sync.aligned.m8n8.x4.shared.b16 {%0,%1,%2,%3}, [%4];"
                 : "=r"(r[0]), "=r"(r[1]), "=r"(r[2]), "=r"(r[3]) : "r"(addr));
}
__device__ __forceinline__ void mma16816(float* c, const uint32_t* a, uint32_t b0, uint32_t b1) {
    asm volatile("mma.sync.aligned.m16n8k16.row.col.f32.bf16.bf16.f32 "
                 "{%0,%1,%2,%3}, {%4,%5,%6,%7}, {%8,%9}, {%0,%1,%2,%3};"
                 : "+f"(c[0]), "+f"(c[1]), "+f"(c[2]), "+f"(c[3])
                 : "r"(a[0]), "r"(a[1]), "r"(a[2]), "r"(a[3]), "r"(b0), "r"(b1));
}
__device__ __forceinline__ void sims_load(uint32_t sbase, const __nv_bfloat16* Ag,
                                          const __nv_bfloat16* Bg, int c, int tid) {
#pragma unroll
    for (int h = 0; h < 2; h++) {
        const __nv_bfloat16* G = h ? Bg : Ag;
        uint32_t base = sbase + (uint32_t)h * 16384;
#pragma unroll
        for (int q = 0; q < 4; q++) {
            int seg = tid + 256 * q;
            int r = seg >> 3, s8 = seg & 7;
            uint32_t dst = base + r * 128 + ((s8 ^ (r & 7)) << 4);
            const char* src = (const char*)(G + (size_t)r * 512 + c * 64 + s8 * 8);
            asm volatile("cp.async.cg.shared.global [%0], [%1], 16;"
                         :: "r"(dst), "l"(src) : "memory");
        }
    }
    asm volatile("cp.async.commit_group;" ::: "memory");
}
#define SIMS_SMEM 66048

__global__ void __launch_bounds__(256, 2) k_mma_sims() {
    int bi = blockIdx.y, bj = blockIdx.x;
    if (bj < bi) return;
    extern __shared__ char smem[];
    uint32_t sb = smem_u32(smem);
    int tid = threadIdx.x;
    int lane = tid & 31, w = tid >> 5;
    int wm = (w & 1) * 64, wn = (w >> 1) * 32;

    const __nv_bfloat16* Ag = d_hb + (size_t)bi * 128 * 512;
    const __nv_bfloat16* Bg = d_hb + (size_t)bj * 128 * 512;

    float acc[4][4][4];
#pragma unroll
    for (int mt = 0; mt < 4; mt++)
#pragma unroll
        for (int nt = 0; nt < 4; nt++)
#pragma unroll
            for (int e = 0; e < 4; e++) acc[mt][nt][e] = 0.f;

    sims_load(sb, Ag, Bg, 0, tid);
    int lr = lane & 15, lks = lane >> 4;
    for (int c = 0; c < 8; c++) {
        if (c < 7) sims_load(sb + ((c + 1) & 1) * 32768, Ag, Bg, c + 1, tid);
        if (c < 7) asm volatile("cp.async.wait_group 1;" ::: "memory");
        else       asm volatile("cp.async.wait_group 0;" ::: "memory");
        __syncthreads();
        uint32_t aB = sb + (c & 1) * 32768, bB = aB + 16384;
#pragma unroll
        for (int ks = 0; ks < 4; ks++) {
            int segk = ks * 2 + lks;
            uint32_t a[4][4], b[2][4];
#pragma unroll
            for (int mt = 0; mt < 4; mt++) {
                int r = wm + mt * 16 + lr;
                ldsm4(a[mt], aB + r * 128 + ((segk ^ (r & 7)) << 4));
            }
#pragma unroll
            for (int bt = 0; bt < 2; bt++) {
                int r = wn + bt * 16 + lr;
                ldsm4(b[bt], bB + r * 128 + ((segk ^ (r & 7)) << 4));
            }
#pragma unroll
            for (int mt = 0; mt < 4; mt++)
#pragma unroll
                for (int nt = 0; nt < 4; nt++)
                    mma16816(acc[mt][nt], a[mt], b[nt >> 1][nt & 1], b[nt >> 1][(nt & 1) + 2]);
        }
        __syncthreads();
    }
    float* sf = (float*)smem;
    int g = lane >> 2, tq = lane & 3;
#pragma unroll
    for (int mt = 0; mt < 4; mt++)
#pragma unroll
        for (int nt = 0; nt < 4; nt++) {
            int r0 = wm + mt * 16 + g, c0 = wn + nt * 8 + tq * 2;
            sf[r0 * 129 + c0]           = acc[mt][nt][0];
            sf[r0 * 129 + c0 + 1]       = acc[mt][nt][1];
            sf[(r0 + 8) * 129 + c0]     = acc[mt][nt][2];
            sf[(r0 + 8) * 129 + c0 + 1] = acc[mt][nt][3];
        }
    __syncthreads();
    size_t gi0 = (size_t)bi * 128, gj0 = (size_t)bj * 128;
    if (bi != bj) {
        for (int it = tid; it < 128 * 64; it += 256) {
            int r = it >> 6, c2 = (it & 63) * 2;
            __nv_bfloat162 p = __floats2bfloat162_rn(sf[r * 129 + c2], sf[r * 129 + c2 + 1]);
            *(__nv_bfloat162*)&d_simh[(gi0 + r) * NN + gj0 + c2] = p;
        }
        for (int it = tid; it < 128 * 64; it += 256) {
            int j = it >> 6, i2 = (it & 63) * 2;
            __nv_bfloat162 p = __floats2bfloat162_rn(sf[i2 * 129 + j], sf[(i2 + 1) * 129 + j]);
            *(__nv_bfloat162*)&d_simh[(gj0 + j) * NN + gi0 + i2] = p;
        }
    } else {
        for (int it = tid; it < 128 * 64; it += 256) {
            int r = it >> 6, c2 = (it & 63) * 2;
            float v0 = (c2 >= r)     ? sf[r * 129 + c2]     : sf[c2 * 129 + r];
            float v1 = (c2 + 1 >= r) ? sf[r * 129 + c2 + 1] : sf[(c2 + 1) * 129 + r];
            __nv_bfloat162 p = __floats2bfloat162_rn(v0, v1);
            *(__nv_bfloat162*)&d_simh[(gi0 + r) * NN + gj0 + c2] = p;
        }
    }
}

// -------- radix-select top-32 (bf16 keys) + exact fp32 rescore -> top-17 --------
__global__ void k_topk(const float* __restrict__ alphap) {
    int row = blockIdx.x, t = threadIdx.x;
    const uint32_t* srow = (const uint32_t*)(d_simh + (size_t)row * NN);  // 4096 u32
    uint32_t kp[16];                                   // 2 keys packed per reg
#pragma unroll
    for (int q = 0; q < 16; q++) {
        uint32_t r = srow[q * 256 + t];
        kp[q] = bf16key(r & 0xFFFFu) | (bf16key(r >> 16) << 16);
    }
    __shared__ int hist[256];
    __shared__ int scn[256];
    __shared__ int sB, sBase, sT, cnum;
    __shared__ int   cand[CANDCAP];
    __shared__ float cex[CANDCAP];
    hist[t] = 0;
    if (t == 0) cnum = 0;
    __syncthreads();
    // pass 1: high-byte histogram
#pragma unroll
    for (int q = 0; q < 16; q++) {
        atomicAdd(&hist[(kp[q] >> 8) & 0xFF], 1);
        atomicAdd(&hist[kp[q] >> 24], 1);
    }
    __syncthreads();
    int hv = hist[t];
    scn[t] = hv;
    __syncthreads();
    // suffix scan: scn[t] = count of keys with high byte >= t
    for (int off = 1; off < 256; off <<= 1) {
        int v = (t + off < 256) ? scn[t + off] : 0;
        __syncthreads();
        scn[t] += v;
        __syncthreads();
    }
    if (scn[t] >= 32 && scn[t] - hv < 32) { sB = t; sBase = scn[t] - hv; }
    __syncthreads();
    int B = sB, base = sBase;
    hist[t] = 0;
    __syncthreads();
    // pass 2: low-byte histogram within bucket B
#pragma unroll
    for (int q = 0; q < 16; q++) {
        uint32_t k0 = kp[q] & 0xFFFFu, k1 = kp[q] >> 16;
        if ((int)(k0 >> 8) == B) atomicAdd(&hist[k0 & 0xFF], 1);
        if ((int)(k1 >> 8) == B) atomicAdd(&hist[k1 & 0xFF], 1);
    }
    __syncthreads();
    int hv2 = hist[t];
    scn[t] = hv2;
    __syncthreads();
    for (int off = 1; off < 256; off <<= 1) {
        int v = (t + off < 256) ? scn[t + off] : 0;
        __syncthreads();
        scn[t] += v;
        __syncthreads();
    }
    int budget = 32 - base;
    if (scn[t] >= budget && scn[t] - hv2 < budget) sT = (B << 8) | t;
    __syncthreads();
    uint32_t T = (uint32_t)sT;
    // pass 3: compact all columns with key >= T
#pragma unroll
    for (int q = 0; q < 16; q++) {
        uint32_t k0 = kp[q] & 0xFFFFu, k1 = kp[q] >> 16;
        int colbase = q * 512 + 2 * t;
        if (k0 >= T) { int pos = atomicAdd(&cnum, 1); if (pos < CANDCAP) cand[pos] = colbase; }
        if (k1 >= T) { int pos = atomicAdd(&cnum, 1); if (pos < CANDCAP) cand[pos] = colbase + 1; }
    }
    __syncthreads();
    int nc = min(cnum, CANDCAP);
    // pass 4: exact fp32 rescore, warp w -> candidates w, w+8, ...
    int w = t >> 5, lane = t & 31;
    const float* hr = d_hn + (size_t)row * 512;
    for (int c = w; c < nc; c += 8) {
        const float* hj = d_hn + (size_t)cand[c] * 512;
        float s = 0.f;
#pragma unroll
        for (int e = 0; e < 16; e++) s += hr[lane + e * 32] * hj[lane + e * 32];
        s = warp_sum(s);
        if (lane == 0) cex[c] = s;
    }
    __syncthreads();
    // pass 5: rank-based parallel selection of top KT by (value desc, index asc)
    if (t < nc) {
        float myv = cex[t]; int myi = cand[t];
        int rank = 0;
        for (int c = 0; c < nc; c++) {
            float v = cex[c]; int ci = cand[c];
            if (v > myv || (v == myv && ci < myi)) rank++;
        }
        if (rank < KT) {
            d_tidx[row * KT + rank] = myi;
            d_tval[row * KT + rank] = (1.f - *alphap) * fmaxf(myv, 0.f);
        }
    }
}

// -------- kNN symmetric CSR build --------
__global__ void k_kcount() {
    int w = (blockIdx.x * 256 + threadIdx.x) >> 5, lane = threadIdx.x & 31;
    if (w >= NN * KT) return;
    int i = w / KT, j = d_tidx[w];
    int cand = (lane < KT) ? d_tidx[j * KT + lane] : -1;
    unsigned f = __ballot_sync(0xffffffffu, cand == i);
    if (lane == 0) {
        atomicAdd(&d_kcnt[i], 1);
        d_kmut[w] = (f != 0);
        if (!f) atomicAdd(&d_kcnt[j], 1);
    }
}
__global__ void k_kscan() {
    __shared__ int bs[256];
    int t = threadIdx.x;
    int loc[32]; int s = 0;
#pragma unroll
    for (int q = 0; q < 32; q++) {
        loc[q] = d_kcnt[t * 32 + q];
        d_kcnt[t * 32 + q] = 0;
        s += loc[q];
    }
    bs[t] = s; __syncthreads();
    for (int off = 1; off < 256; off <<= 1) {
        int v = (t >= off) ? bs[t - off] : 0;
        __syncthreads();
        bs[t] += v;
        __syncthreads();
    }
    int run = bs[t] - s;
#pragma unroll
    for (int q = 0; q < 32; q++) {
        int i = t * 32 + q;
        d_kptr[i] = run; d_kcur[i] = run;
        run += loc[q];
    }
    if (t == 255) d_kptr[NN] = run;
}
__global__ void k_kfill() {
    int w = blockIdx.x * 256 + threadIdx.x;
    if (w >= NN * KT) return;
    int i = w / KT, j = d_tidx[w];
    float v = d_tval[w];
    int pos = atomicAdd(&d_kcur[i], 1);
    d_kidx[pos] = j; d_kval[pos] = v;
    if (!d_kmut[w]) {
        int pos2 = atomicAdd(&d_kcur[j], 1);
        d_kidx[pos2] = i; d_kval[pos2] = v;
    }
}

// -------- dense [8192,256]@[256,256] fp32 GEMM --------
template <int L>
__global__ void k_sgemm_nn(const float* __restrict__ W) {
    const float* A = (L == 0) ? d_fea : d_h1;
    float* C = (L == 0) ? d_xw : d_hw;
    int bm = blockIdx.y, bn = blockIdx.x;
    __shared__ float As[16][132];
    __shared__ float Bs[16][132];
    int tid = threadIdx.x, tm = tid >> 4, tn = tid & 15;
    float acc[8][8];
#pragma unroll
    for (int u = 0; u < 8; u++)
#pragma unroll
        for (int v = 0; v < 8; v++) acc[u][v] = 0.f;
    int r = tid >> 1, kc = (tid & 1) * 8;
    int kb = tid >> 4, nb = (tid & 15) * 8;
    for (int k0 = 0; k0 < 256; k0 += 16) {
        float4 a0 = *(const float4*)&A[(size_t)(bm*128+r)*256 + k0 + kc];
        float4 a1 = *(const float4*)&A[(size_t)(bm*128+r)*256 + k0 + kc + 4];
        float4 b0 = *(const float4*)&W[(size_t)(k0+kb)*256 + bn*128 + nb];
        float4 b1 = *(const float4*)&W[(size_t)(k0+kb)*256 + bn*128 + nb + 4];
        __syncthreads();
        As[kc+0][r]=a0.x; As[kc+1][r]=a0.y; As[kc+2][r]=a0.z; As[kc+3][r]=a0.w;
        As[kc+4][r]=a1.x; As[kc+5][r]=a1.y; As[kc+6][r]=a1.z; As[kc+7][r]=a1.w;
        *(float4*)&Bs[kb][nb] = b0;
        *(float4*)&Bs[kb][nb+4] = b1;
        __syncthreads();
#pragma unroll
        for (int kk = 0; kk < 16; kk++) {
            float av[8], bv[8];
#pragma unroll
            for (int u = 0; u < 8; u++) { av[u]=As[kk][tm*8+u]; bv[u]=Bs[kk][tn*8+u]; }
#pragma unroll
            for (int u = 0; u < 8; u++)
#pragma unroll
                for (int vv = 0; vv < 8; vv++) acc[u][vv] += av[u]*bv[vv];
        }
    }
#pragma unroll
    for (int u = 0; u < 8; u++) {
        float* crow = &C[(size_t)(bm*128+tm*8+u)*256 + bn*128 + tn*8];
        *(float4*)crow     = make_float4(acc[u][0],acc[u][1],acc[u][2],acc[u][3]);
        *(float4*)(crow+4) = make_float4(acc[u][4],acc[u][5],acc[u][6],acc[u][7]);
    }
}

// -------- gather-based A_tot @ X --------
template <int L>
__global__ void k_spmm_gather(const float* __restrict__ alphap) {
    int gw = (blockIdx.x * 256 + threadIdx.x) >> 5, lane = threadIdx.x & 31;
    if (gw >= NN) return;
    const float* X = (L == 0) ? d_xw : d_hw;
    float* out = (L == 0) ? d_h1 : d_emb;
    float alpha = *alphap;
    float di = d_dinv[gw];
    const float4* xr = (const float4*)(X + (size_t)gw * 256);
    float4 x0 = xr[lane], x1 = xr[lane + 32];
    float sc = di * di;
    float4 a0 = make_float4(sc*x0.x, sc*x0.y, sc*x0.z, sc*x0.w);
    float4 a1 = make_float4(sc*x1.x, sc*x1.y, sc*x1.z, sc*x1.w);
    int b = d_rptr[gw], e = d_rptr[gw + 1];
    int p = b;
    for (; p + 1 < e; p += 2) {
        float w0 = d_cw[p], w1 = d_cw[p + 1];
        const float4* s0 = (const float4*)(X + (size_t)d_csrc[p] * 256);
        const float4* s1 = (const float4*)(X + (size_t)d_csrc[p + 1] * 256);
        float4 v00 = s0[lane], v01 = s0[lane + 32];
        float4 v10 = s1[lane], v11 = s1[lane + 32];
        fma4(a0, w0, v00); fma4(a1, w0, v01);
        fma4(a0, w1, v10); fma4(a1, w1, v11);
    }
    if (p < e) {
        float wv = d_cw[p];
        const float4* xs = (const float4*)(X + (size_t)d_csrc[p] * 256);
        fma4(a0, wv, xs[lane]); fma4(a1, wv, xs[lane + 32]);
    }
    a0.x*=alpha; a0.y*=alpha; a0.z*=alpha; a0.w*=alpha;
    a1.x*=alpha; a1.y*=alpha; a1.z*=alpha; a1.w*=alpha;
    int kb = d_kptr[gw], ke = d_kptr[gw + 1];
    p = kb;
    for (; p + 1 < ke; p += 2) {
        float w0 = d_kval[p], w1 = d_kval[p + 1];
        const float4* s0 = (const float4*)(X + (size_t)d_kidx[p] * 256);
        const float4* s1 = (const float4*)(X + (size_t)d_kidx[p + 1] * 256);
        float4 v00 = s0[lane], v01 = s0[lane + 32];
        float4 v10 = s1[lane], v11 = s1[lane + 32];
        fma4(a0, w0, v00); fma4(a1, w0, v01);
        fma4(a0, w1, v10); fma4(a1, w1, v11);
    }
    if (p < ke) {
        float v = d_kval[p];
        const float4* xs = (const float4*)(X + (size_t)d_kidx[p] * 256);
        fma4(a0, v, xs[lane]); fma4(a1, v, xs[lane + 32]);
    }
    if (L == 0) {
        a0.x=fmaxf(a0.x,0.f); a0.y=fmaxf(a0.y,0.f); a0.z=fmaxf(a0.z,0.f); a0.w=fmaxf(a0.w,0.f);
        a1.x=fmaxf(a1.x,0.f); a1.y=fmaxf(a1.y,0.f); a1.z=fmaxf(a1.z,0.f); a1.w=fmaxf(a1.w,0.f);
    }
    float4* orow = (float4*)(out + (size_t)gw * 256);
    orow[lane] = a0; orow[lane + 32] = a1;
}

// -------- classification --------
__global__ void k_cls_scatter(const int* __restrict__ labels, const int* __restrict__ nidx) {
    int w = (blockIdx.x*256+threadIdx.x) >> 5, lane = threadIdx.x & 31;
    if (w >= NSEL) return;
    int lbl = labels[w];
    const float4* er = (const float4*)(d_emb + (size_t)nidx[w]*HIDD);
    float4* sr = (float4*)(d_sums + lbl*HIDD);
#pragma unroll
    for (int q = 0; q < 2; q++) {
        int f = lane + 32*q; float4 v = er[f];
        red4(&sr[f], v.x, v.y, v.z, v.w);
    }
    if (lane == 0) atomicAdd(&d_cnt[lbl], 1.f);
}
__global__ void k_proto() {
    int c = blockIdx.x, t = threadIdx.x;
    float cnt = d_cnt[c];
    float sm = d_sums[c*HIDD+t];
    float p = sm / fmaxf(cnt, 1.f);
    __shared__ float red[256];
    red[t] = p*p;
    __syncthreads();
    for (int s = 128; s > 0; s >>= 1) { if (t < s) red[t] += red[t+s]; __syncthreads(); }
    d_pn[c*HIDD+t] = p / (sqrtf(red[0]) + EPSF);
    d_sums[c*HIDD+t] = 0.f;
    if (t == 0) d_cnt[c] = 0.f;
}
__global__ void k_out(const int* __restrict__ nidx, float* __restrict__ out) {
    int w = (blockIdx.x*256+threadIdx.x) >> 5, lane = threadIdx.x & 31;
    if (w >= NSEL) return;
    const float* er = d_emb + (size_t)nidx[w]*HIDD;
    float v[8]; float ss = 0.f;
#pragma unroll
    for (int q = 0; q < 8; q++) { v[q] = er[lane+32*q]; ss += v[q]*v[q]; }
    ss = warp_sum(ss);
    float rn = 1.f / (sqrtf(ss) + EPSF);
#pragma unroll
    for (int c = 0; c < NCLS; c++) {
        float dp = 0.f;
#pragma unroll
        for (int q = 0; q < 8; q++) dp += v[q] * d_pn[c*HIDD + lane + 32*q];
        dp = warp_sum(dp);
        if (lane == 0) out[w*NCLS + c] = dp * rn * 5.0f;
    }
}

extern "C" void kernel_launch(void* const* d_in, const int* in_sizes, int n_in,
                              void* d_out, int out_size) {
    const float* x   = (const float*)d_in[0];
    const float* cw  = (const float*)d_in[1];
    const float* alp = (const float*)d_in[2];
    const float* ps  = (const float*)d_in[3];
    const float* st  = (const float*)d_in[4];
    const float* bal = (const float*)d_in[5];
    const float* W1  = (const float*)d_in[6];
    const float* W2  = (const float*)d_in[7];
    const int*   ei  = (const int*)d_in[8];
    const int*   lab = (const int*)d_in[9];
    const int*   nix = (const int*)d_in[10];
    float* out = (float*)d_out;
    const int* esrc = ei;
    const int* edst = ei + NE;

    cudaFuncSetAttribute(k_mma_sims, cudaFuncAttributeMaxDynamicSharedMemorySize, SIMS_SMEM);

    k_fea<<<NN*FIN/256, 256>>>(x, cw, ps, st, edst);
    k_scan<<<1, 256>>>();
    k_fill<<<NE/256, 256>>>(esrc, edst);
    k_agg_h<<<NN/8, 256>>>(bal);
    k_mma_sims<<<dim3(64, 64), 256, SIMS_SMEM>>>();
    k_topk<<<NN, 256>>>(alp);
    k_kcount<<<NN*KT/8, 256>>>();
    k_kscan<<<1, 256>>>();
    k_kfill<<<(NN*KT+255)/256, 256>>>();

    k_sgemm_nn<0><<<dim3(2, 64), 256>>>(W1);
    k_spmm_gather<0><<<NN/8, 256>>>(alp);
    k_sgemm_nn<1><<<dim3(2, 64), 256>>>(W2);
    k_spmm_gather<1><<<NN/8, 256>>>(alp);

    k_cls_scatter<<<NSEL/8, 256>>>(lab, nix);
    k_proto<<<NCLS, 256>>>();
    k_out<<<NSEL/8, 256>>>(nix, out);
}

// round 10
// speedup vs baseline: 2.8085x; 1.2265x over previous
#include <cuda_runtime.h>
#include <cuda_bf16.h>
#include <math.h>
#include <float.h>
#include <stdint.h>

#define NN   8192
#define FIN  256
#define HIDD 256
#define NE   131072
#define KT   17
#define CANDCAP 96
#define NCLS 10
#define NSEL 4096
#define EPSF 1e-8f

__device__ __align__(16) float d_fea[NN * FIN];
__device__ __align__(16) __nv_bfloat16 d_feah[NN * FIN];
__device__ __align__(16) __nv_bfloat16 d_feal[NN * FIN];
__device__ float d_dinv[NN];
__device__ int   d_cnt_e[NN];          // self-clean in k_scan
__device__ int   d_rptr[NN + 1];
__device__ int   d_cur[NN];
__device__ int   d_csrc[NE];
__device__ float d_cw[NE];
__device__ __align__(16) float d_hn[NN * 512];
__device__ __align__(16) __nv_bfloat16 d_hb[NN * 512];
__device__ __nv_bfloat16 d_simh[(size_t)NN * NN];
__device__ int   d_tidx[NN * KT];
__device__ float d_tval[NN * KT];
__device__ int   d_kcnt[NN];           // self-clean in k_kscan
__device__ int   d_kptr[NN + 1];
__device__ int   d_kcur[NN];
__device__ unsigned char d_kmut[NN * KT];
__device__ int   d_kidx[NN * KT * 2];
__device__ float d_kval[NN * KT * 2];
__device__ __align__(16) __nv_bfloat16 d_w1h[FIN * HIDD];
__device__ __align__(16) __nv_bfloat16 d_w1l[FIN * HIDD];
__device__ __align__(16) __nv_bfloat16 d_w2h[HIDD * HIDD];
__device__ __align__(16) __nv_bfloat16 d_w2l[HIDD * HIDD];
__device__ __align__(16) float d_xw[NN * HIDD];
__device__ __align__(16) float d_h1[NN * HIDD];
__device__ __align__(16) __nv_bfloat16 d_h1h[NN * HIDD];
__device__ __align__(16) __nv_bfloat16 d_h1l[NN * HIDD];
__device__ __align__(16) float d_hw[NN * HIDD];
__device__ __align__(16) float d_emb[NN * HIDD];
__device__ __align__(16) float d_sums[NCLS * HIDD]; // self-clean in k_proto
__device__ float d_cnt[NCLS];                       // self-clean in k_proto
__device__ float d_pn[NCLS * HIDD];

__device__ __forceinline__ float warp_sum(float v) {
#pragma unroll
    for (int o = 16; o > 0; o >>= 1) v += __shfl_xor_sync(0xffffffffu, v, o);
    return v;
}
__device__ __forceinline__ void red4(float4* addr, float a, float b, float c, float d) {
    asm volatile("red.global.add.v4.f32 [%0], {%1,%2,%3,%4};"
                 :: "l"(addr), "f"(a), "f"(b), "f"(c), "f"(d) : "memory");
}
__device__ __forceinline__ void fma4(float4& a, float w, const float4 v) {
    a.x += w * v.x; a.y += w * v.y; a.z += w * v.z; a.w += w * v.w;
}
__device__ __forceinline__ uint2 pack_bf16x4(float4 v) {
    __nv_bfloat162 lo = __floats2bfloat162_rn(v.x, v.y);
    __nv_bfloat162 hi = __floats2bfloat162_rn(v.z, v.w);
    uint2 r;
    r.x = *reinterpret_cast<uint32_t*>(&lo);
    r.y = *reinterpret_cast<uint32_t*>(&hi);
    return r;
}
__device__ __forceinline__ uint32_t bf16key(uint32_t b) {  // monotone 16-bit key
    return (b & 0x8000u) ? (~b & 0xFFFFu) : (b | 0x8000u);
}

// -------- weight transpose + hi/lo split (W1, W2 -> Wt) --------
__global__ void k_wpack(const float* __restrict__ W1, const float* __restrict__ W2) {
    int idx = blockIdx.x * 256 + threadIdx.x;   // 0..131071
    int wsel = idx >> 16;
    int e = idx & 0xFFFF;
    int k = e >> 8, n = e & 255;
    float v = (wsel ? W2 : W1)[e];
    __nv_bfloat16 hi = __float2bfloat16(v);
    __nv_bfloat16 lo = __float2bfloat16(v - __bfloat162float(hi));
    (wsel ? d_w2h : d_w1h)[n * 256 + k] = hi;
    (wsel ? d_w2l : d_w1l)[n * 256 + k] = lo;
}

// -------- fea = elu(...) + hi/lo split + degree count --------
__global__ void k_fea(const float* __restrict__ x, const float* __restrict__ cw,
                      const float* __restrict__ ps, const float* __restrict__ st,
                      const int* __restrict__ dst) {
    int idx = blockIdx.x * 256 + threadIdx.x;
    int f = idx & (FIN - 1);
    float z = x[idx] * (cw[0] * ps[f] + cw[1] * st[f]);
    float r = z > 0.f ? z : expm1f(z);
    d_fea[idx] = r;
    __nv_bfloat16 hi = __float2bfloat16(r);
    d_feah[idx] = hi;
    d_feal[idx] = __float2bfloat16(r - __bfloat162float(hi));
    if (idx < NE) atomicAdd(&d_cnt_e[dst[idx]], 1);
}
// -------- scan (+self-clean counts) --------
__global__ void k_scan() {
    __shared__ int bs[256];
    int t = threadIdx.x;
    int loc[32]; int s = 0;
#pragma unroll
    for (int q = 0; q < 32; q++) {
        loc[q] = d_cnt_e[t * 32 + q];
        d_cnt_e[t * 32 + q] = 0;
        s += loc[q];
    }
    bs[t] = s; __syncthreads();
    for (int off = 1; off < 256; off <<= 1) {
        int v = (t >= off) ? bs[t - off] : 0;
        __syncthreads();
        bs[t] += v;
        __syncthreads();
    }
    int run = bs[t] - s;
#pragma unroll
    for (int q = 0; q < 32; q++) {
        int i = t * 32 + q;
        d_rptr[i] = run; d_cur[i] = run;
        d_dinv[i] = rsqrtf((float)(loc[q] + 1));
        run += loc[q];
    }
    if (t == 255) d_rptr[NN] = run;
}
__global__ void k_fill(const int* __restrict__ src, const int* __restrict__ dst) {
    int e = blockIdx.x * 256 + threadIdx.x;
    if (e >= NE) return;
    int s = src[e], d = dst[e];
    int pos = atomicAdd(&d_cur[d], 1);
    d_csrc[pos] = s;
    d_cw[pos] = d_dinv[s] * d_dinv[d];
}
// -------- fused aggregate-gather + h-normalize + bf16 --------
__global__ void k_agg_h(const float* __restrict__ bal) {
    int gw = (blockIdx.x * 256 + threadIdx.x) >> 5, lane = threadIdx.x & 31;
    if (gw >= NN) return;
    float di = d_dinv[gw];
    const float4* fr = (const float4*)(d_fea + (size_t)gw * 256);
    float4 f0 = fr[lane], f1 = fr[lane + 32];
    float sc = di * di;
    float4 a0 = make_float4(sc*f0.x, sc*f0.y, sc*f0.z, sc*f0.w);
    float4 a1 = make_float4(sc*f1.x, sc*f1.y, sc*f1.z, sc*f1.w);
    int b = d_rptr[gw], e = d_rptr[gw + 1];
    int p = b;
    for (; p + 1 < e; p += 2) {
        float w0 = d_cw[p], w1 = d_cw[p + 1];
        const float4* s0 = (const float4*)(d_fea + (size_t)d_csrc[p] * 256);
        const float4* s1 = (const float4*)(d_fea + (size_t)d_csrc[p + 1] * 256);
        float4 v00 = s0[lane], v01 = s0[lane + 32];
        float4 v10 = s1[lane], v11 = s1[lane + 32];
        fma4(a0, w0, v00); fma4(a1, w0, v01);
        fma4(a0, w1, v10); fma4(a1, w1, v11);
    }
    if (p < e) {
        float wv = d_cw[p];
        const float4* fs = (const float4*)(d_fea + (size_t)d_csrc[p] * 256);
        fma4(a0, wv, fs[lane]); fma4(a1, wv, fs[lane + 32]);
    }
    const float4* bb = (const float4*)bal;
    float4 bA = bb[lane], bB = bb[lane + 32], bC = bb[64 + lane], bD = bb[96 + lane];
    float4 hA = make_float4(f0.x*bA.x, f0.y*bA.y, f0.z*bA.z, f0.w*bA.w);
    float4 hB = make_float4(f1.x*bB.x, f1.y*bB.y, f1.z*bB.z, f1.w*bB.w);
    float4 hC = make_float4(a0.x*bC.x, a0.y*bC.y, a0.z*bC.z, a0.w*bC.w);
    float4 hD = make_float4(a1.x*bD.x, a1.y*bD.y, a1.z*bD.z, a1.w*bD.w);
    float ss = hA.x*hA.x+hA.y*hA.y+hA.z*hA.z+hA.w*hA.w
             + hB.x*hB.x+hB.y*hB.y+hB.z*hB.z+hB.w*hB.w
             + hC.x*hC.x+hC.y*hC.y+hC.z*hC.z+hC.w*hC.w
             + hD.x*hD.x+hD.y*hD.y+hD.z*hD.z+hD.w*hD.w;
    ss = warp_sum(ss);
    float rn = 1.f / (sqrtf(ss) + EPSF);
    hA.x*=rn; hA.y*=rn; hA.z*=rn; hA.w*=rn;
    hB.x*=rn; hB.y*=rn; hB.z*=rn; hB.w*=rn;
    hC.x*=rn; hC.y*=rn; hC.z*=rn; hC.w*=rn;
    hD.x*=rn; hD.y*=rn; hD.z*=rn; hD.w*=rn;
    float4* hr = (float4*)(d_hn + (size_t)gw * 512);
    hr[lane] = hA; hr[lane + 32] = hB; hr[64 + lane] = hC; hr[96 + lane] = hD;
    uint2* hb = (uint2*)(d_hb + (size_t)gw * 512);
    hb[lane] = pack_bf16x4(hA); hb[lane + 32] = pack_bf16x4(hB);
    hb[64 + lane] = pack_bf16x4(hC); hb[96 + lane] = pack_bf16x4(hD);
}

// ======== mma helpers ========
__device__ __forceinline__ uint32_t smem_u32(const void* p) {
    uint32_t a;
    asm("{ .reg .u64 t; cvta.to.shared.u64 t, %1; cvt.u32.u64 %0, t; }" : "=r"(a) : "l"(p));
    return a;
}
__device__ __forceinline__ void ldsm4(uint32_t* r, uint32_t addr) {
    asm volatile("ldmatrix.sync.aligned.m8n8.x4.shared.b16 {%0,%1,%2,%3}, [%4];"
                 : "=r"(r[0]), "=r"(r[1]), "=r"(r[2]), "=r"(r[3]) : "r"(addr));
}
__device__ __forceinline__ void mma16816(float* c, const uint32_t* a, uint32_t b0, uint32_t b1) {
    asm volatile("mma.sync.aligned.m16n8k16.row.col.f32.bf16.bf16.f32 "
                 "{%0,%1,%2,%3}, {%4,%5,%6,%7}, {%8,%9}, {%0,%1,%2,%3};"
                 : "+f"(c[0]), "+f"(c[1]), "+f"(c[2]), "+f"(c[3])
                 : "r"(a[0]), "r"(a[1]), "r"(a[2]), "r"(a[3]), "r"(b0), "r"(b1));
}
__device__ __forceinline__ void sims_load(uint32_t sbase, const __nv_bfloat16* Ag,
                                          const __nv_bfloat16* Bg, int c, int tid) {
#pragma unroll
    for (int h = 0; h < 2; h++) {
        const __nv_bfloat16* G = h ? Bg : Ag;
        uint32_t base = sbase + (uint32_t)h * 16384;
#pragma unroll
        for (int q = 0; q < 4; q++) {
            int seg = tid + 256 * q;
            int r = seg >> 3, s8 = seg & 7;
            uint32_t dst = base + r * 128 + ((s8 ^ (r & 7)) << 4);
            const char* src = (const char*)(G + (size_t)r * 512 + c * 64 + s8 * 8);
            asm volatile("cp.async.cg.shared.global [%0], [%1], 16;"
                         :: "r"(dst), "l"(src) : "memory");
        }
    }
    asm volatile("cp.async.commit_group;" ::: "memory");
}
// 128 rows x 64 bf16 tile from a row-stride-256 matrix
__device__ __forceinline__ void gload(uint32_t dst_base, const __nv_bfloat16* G,
                                      int k0, int tid) {
#pragma unroll
    for (int q = 0; q < 4; q++) {
        int seg = tid + 256 * q;
        int r = seg >> 3, s8 = seg & 7;
        uint32_t dst = dst_base + r * 128 + ((s8 ^ (r & 7)) << 4);
        const char* src = (const char*)(G + (size_t)r * 256 + k0 + s8 * 8);
        asm volatile("cp.async.cg.shared.global [%0], [%1], 16;"
                     :: "r"(dst), "l"(src) : "memory");
    }
}
#define SIMS_SMEM 66048

// ======== sims = hb @ hb^T, upper-triangle tiles only ========
__global__ void __launch_bounds__(256, 2) k_mma_sims() {
    int idx = blockIdx.x;
    int bj = (int)((sqrtf(8.f * idx + 1.f) - 1.f) * 0.5f);
    while ((bj + 1) * (bj + 2) / 2 <= idx) bj++;
    while (bj * (bj + 1) / 2 > idx) bj--;
    int bi = idx - bj * (bj + 1) / 2;           // bi <= bj
    extern __shared__ char smem[];
    uint32_t sb = smem_u32(smem);
    int tid = threadIdx.x;
    int lane = tid & 31, w = tid >> 5;
    int wm = (w & 1) * 64, wn = (w >> 1) * 32;

    const __nv_bfloat16* Ag = d_hb + (size_t)bi * 128 * 512;
    const __nv_bfloat16* Bg = d_hb + (size_t)bj * 128 * 512;

    float acc[4][4][4];
#pragma unroll
    for (int mt = 0; mt < 4; mt++)
#pragma unroll
        for (int nt = 0; nt < 4; nt++)
#pragma unroll
            for (int e = 0; e < 4; e++) acc[mt][nt][e] = 0.f;

    sims_load(sb, Ag, Bg, 0, tid);
    int lr = lane & 15, lks = lane >> 4;
    for (int c = 0; c < 8; c++) {
        if (c < 7) sims_load(sb + ((c + 1) & 1) * 32768, Ag, Bg, c + 1, tid);
        if (c < 7) asm volatile("cp.async.wait_group 1;" ::: "memory");
        else       asm volatile("cp.async.wait_group 0;" ::: "memory");
        __syncthreads();
        uint32_t aB = sb + (c & 1) * 32768, bB = aB + 16384;
#pragma unroll
        for (int ks = 0; ks < 4; ks++) {
            int segk = ks * 2 + lks;
            uint32_t a[4][4], b[2][4];
#pragma unroll
            for (int mt = 0; mt < 4; mt++) {
                int r = wm + mt * 16 + lr;
                ldsm4(a[mt], aB + r * 128 + ((segk ^ (r & 7)) << 4));
            }
#pragma unroll
            for (int bt = 0; bt < 2; bt++) {
                int r = wn + bt * 16 + lr;
                ldsm4(b[bt], bB + r * 128 + ((segk ^ (r & 7)) << 4));
            }
#pragma unroll
            for (int mt = 0; mt < 4; mt++)
#pragma unroll
                for (int nt = 0; nt < 4; nt++)
                    mma16816(acc[mt][nt], a[mt], b[nt >> 1][nt & 1], b[nt >> 1][(nt & 1) + 2]);
        }
        __syncthreads();
    }
    float* sf = (float*)smem;
    int g = lane >> 2, tq = lane & 3;
#pragma unroll
    for (int mt = 0; mt < 4; mt++)
#pragma unroll
        for (int nt = 0; nt < 4; nt++) {
            int r0 = wm + mt * 16 + g, c0 = wn + nt * 8 + tq * 2;
            sf[r0 * 129 + c0]           = acc[mt][nt][0];
            sf[r0 * 129 + c0 + 1]       = acc[mt][nt][1];
            sf[(r0 + 8) * 129 + c0]     = acc[mt][nt][2];
            sf[(r0 + 8) * 129 + c0 + 1] = acc[mt][nt][3];
        }
    __syncthreads();
    size_t gi0 = (size_t)bi * 128, gj0 = (size_t)bj * 128;
    if (bi != bj) {
        for (int it = tid; it < 128 * 64; it += 256) {
            int r = it >> 6, c2 = (it & 63) * 2;
            __nv_bfloat162 p = __floats2bfloat162_rn(sf[r * 129 + c2], sf[r * 129 + c2 + 1]);
            *(__nv_bfloat162*)&d_simh[(gi0 + r) * NN + gj0 + c2] = p;
        }
        for (int it = tid; it < 128 * 64; it += 256) {
            int j = it >> 6, i2 = (it & 63) * 2;
            __nv_bfloat162 p = __floats2bfloat162_rn(sf[i2 * 129 + j], sf[(i2 + 1) * 129 + j]);
            *(__nv_bfloat162*)&d_simh[(gj0 + j) * NN + gi0 + i2] = p;
        }
    } else {
        for (int it = tid; it < 128 * 64; it += 256) {
            int r = it >> 6, c2 = (it & 63) * 2;
            float v0 = (c2 >= r)     ? sf[r * 129 + c2]     : sf[c2 * 129 + r];
            float v1 = (c2 + 1 >= r) ? sf[r * 129 + c2 + 1] : sf[(c2 + 1) * 129 + r];
            __nv_bfloat162 p = __floats2bfloat162_rn(v0, v1);
            *(__nv_bfloat162*)&d_simh[(gi0 + r) * NN + gj0 + c2] = p;
        }
    }
}

// -------- topk: max-relative bins + prefilter + exact rescore --------
__global__ void k_topk(const float* __restrict__ alphap) {
    int row = blockIdx.x, t = threadIdx.x;
    int w = t >> 5, lane = t & 31;
    const uint32_t* srow = (const uint32_t*)(d_simh + (size_t)row * NN);
    uint32_t kp[16];
#pragma unroll
    for (int q = 0; q < 16; q++) {
        uint32_t r = srow[q * 256 + t];
        kp[q] = bf16key(r & 0xFFFFu) | (bf16key(r >> 16) << 16);
    }
    __shared__ int hist[256];
    __shared__ int scn[256];
    __shared__ uint32_t sMax[8];
    __shared__ int sB, cnum;
    __shared__ int   cand[CANDCAP];
    __shared__ float cex[CANDCAP];
    hist[t] = 0;
    if (t == 0) { cnum = 0; sB = 255; }
    // block max key
    uint32_t mk = 0;
#pragma unroll
    for (int q = 0; q < 16; q++) {
        uint32_t a = kp[q] & 0xFFFFu, b2 = kp[q] >> 16;
        mk = max(mk, max(a, b2));
    }
#pragma unroll
    for (int o = 16; o > 0; o >>= 1)
        mk = max(mk, __shfl_xor_sync(0xffffffffu, mk, o));
    if (lane == 0) sMax[w] = mk;
    __syncthreads();
    uint32_t Kmax = sMax[0];
#pragma unroll
    for (int q = 1; q < 8; q++) Kmax = max(Kmax, sMax[q]);
    // histogram on (Kmax - key) >> 2; only nearby keys binned
#pragma unroll
    for (int q = 0; q < 16; q++) {
        uint32_t d0 = (Kmax - (kp[q] & 0xFFFFu)) >> 2;
        uint32_t d1 = (Kmax - (kp[q] >> 16)) >> 2;
        if (d0 < 256) atomicAdd(&hist[d0], 1);
        if (d1 < 256) atomicAdd(&hist[d1], 1);
    }
    __syncthreads();
    int hv = hist[t];
    scn[t] = hv;
    __syncthreads();
    for (int off = 1; off < 256; off <<= 1) {   // inclusive prefix (descending keys)
        int v = (t >= off) ? scn[t - off] : 0;
        __syncthreads();
        scn[t] += v;
        __syncthreads();
    }
    if (scn[t] >= 32 && scn[t] - hv < 32) sB = t;
    __syncthreads();
    int B = sB;
    // compaction
#pragma unroll
    for (int q = 0; q < 16; q++) {
        uint32_t d0 = (Kmax - (kp[q] & 0xFFFFu)) >> 2;
        uint32_t d1 = (Kmax - (kp[q] >> 16)) >> 2;
        int colbase = q * 512 + 2 * t;
        if ((int)d0 <= B) { int pos = atomicAdd(&cnum, 1); if (pos < CANDCAP) cand[pos] = colbase; }
        if ((int)d1 <= B) { int pos = atomicAdd(&cnum, 1); if (pos < CANDCAP) cand[pos] = colbase + 1; }
    }
    __syncthreads();
    int nc = min(cnum, CANDCAP);
    // exact fp32 rescore
    const float* hr = d_hn + (size_t)row * 512;
    for (int c = w; c < nc; c += 8) {
        const float* hj = d_hn + (size_t)cand[c] * 512;
        float s = 0.f;
#pragma unroll
        for (int e = 0; e < 16; e++) s += hr[lane + e * 32] * hj[lane + e * 32];
        s = warp_sum(s);
        if (lane == 0) cex[c] = s;
    }
    __syncthreads();
    // rank-based top-KT by (value desc, index asc)
    if (t < nc) {
        float myv = cex[t]; int myi = cand[t];
        int rank = 0;
        for (int c = 0; c < nc; c++) {
            float v = cex[c]; int ci = cand[c];
            if (v > myv || (v == myv && ci < myi)) rank++;
        }
        if (rank < KT) {
            d_tidx[row * KT + rank] = myi;
            d_tval[row * KT + rank] = (1.f - *alphap) * fmaxf(myv, 0.f);
        }
    }
}

// -------- kNN symmetric CSR build --------
__global__ void k_kcount() {
    int w = (blockIdx.x * 256 + threadIdx.x) >> 5, lane = threadIdx.x & 31;
    if (w >= NN * KT) return;
    int i = w / KT, j = d_tidx[w];
    int cand = (lane < KT) ? d_tidx[j * KT + lane] : -1;
    unsigned f = __ballot_sync(0xffffffffu, cand == i);
    if (lane == 0) {
        atomicAdd(&d_kcnt[i], 1);
        d_kmut[w] = (f != 0);
        if (!f) atomicAdd(&d_kcnt[j], 1);
    }
}
__global__ void k_kscan() {
    __shared__ int bs[256];
    int t = threadIdx.x;
    int loc[32]; int s = 0;
#pragma unroll
    for (int q = 0; q < 32; q++) {
        loc[q] = d_kcnt[t * 32 + q];
        d_kcnt[t * 32 + q] = 0;
        s += loc[q];
    }
    bs[t] = s; __syncthreads();
    for (int off = 1; off < 256; off <<= 1) {
        int v = (t >= off) ? bs[t - off] : 0;
        __syncthreads();
        bs[t] += v;
        __syncthreads();
    }
    int run = bs[t] - s;
#pragma unroll
    for (int q = 0; q < 32; q++) {
        int i = t * 32 + q;
        d_kptr[i] = run; d_kcur[i] = run;
        run += loc[q];
    }
    if (t == 255) d_kptr[NN] = run;
}
__global__ void k_kfill() {
    int w = blockIdx.x * 256 + threadIdx.x;
    if (w >= NN * KT) return;
    int i = w / KT, j = d_tidx[w];
    float v = d_tval[w];
    int pos = atomicAdd(&d_kcur[i], 1);
    d_kidx[pos] = j; d_kval[pos] = v;
    if (!d_kmut[w]) {
        int pos2 = atomicAdd(&d_kcur[j], 1);
        d_kidx[pos2] = i; d_kval[pos2] = v;
    }
}

// -------- bf16 split GEMM: C[8192,256] = A @ W (3-term hi/lo) --------
template <int L>
__global__ void __launch_bounds__(256) k_gemm_bf16() {
    int bn = blockIdx.x, bm = blockIdx.y;
    extern __shared__ char smem[];
    uint32_t sb = smem_u32(smem);
    int tid = threadIdx.x, lane = tid & 31, w = tid >> 5;
    int wm = (w & 1) * 64, wn = (w >> 1) * 32;
    const __nv_bfloat16* Ah = (L ? d_h1h : d_feah) + (size_t)bm * 128 * 256;
    const __nv_bfloat16* Al = (L ? d_h1l : d_feal) + (size_t)bm * 128 * 256;
    const __nv_bfloat16* Bh = (L ? d_w2h : d_w1h) + (size_t)bn * 128 * 256;
    const __nv_bfloat16* Bl = (L ? d_w2l : d_w1l) + (size_t)bn * 128 * 256;
    float* C = L ? d_hw : d_xw;

    float acc[4][4][4];
#pragma unroll
    for (int mt = 0; mt < 4; mt++)
#pragma unroll
        for (int nt = 0; nt < 4; nt++)
#pragma unroll
            for (int e = 0; e < 4; e++) acc[mt][nt][e] = 0.f;

    int lr = lane & 15, lks = lane >> 4;
    for (int c = 0; c < 4; c++) {
        int k0 = c * 64;
        gload(sb,         Ah, k0, tid);
        gload(sb + 16384, Al, k0, tid);
        gload(sb + 32768, Bh, k0, tid);
        gload(sb + 49152, Bl, k0, tid);
        asm volatile("cp.async.commit_group;" ::: "memory");
        asm volatile("cp.async.wait_group 0;" ::: "memory");
        __syncthreads();
#pragma unroll
        for (int ks = 0; ks < 4; ks++) {
            int segk = ks * 2 + lks;
            uint32_t a[4][4], bh[2][4], bl[2][4];
#pragma unroll
            for (int bt = 0; bt < 2; bt++) {
                int r = wn + bt * 16 + lr;
                uint32_t off = r * 128 + ((segk ^ (r & 7)) << 4);
                ldsm4(bh[bt], sb + 32768 + off);
                ldsm4(bl[bt], sb + 49152 + off);
            }
#pragma unroll
            for (int mt = 0; mt < 4; mt++) {
                int r = wm + mt * 16 + lr;
                ldsm4(a[mt], sb + r * 128 + ((segk ^ (r & 7)) << 4));
            }
#pragma unroll
            for (int mt = 0; mt < 4; mt++)
#pragma unroll
                for (int nt = 0; nt < 4; nt++) {
                    mma16816(acc[mt][nt], a[mt], bh[nt >> 1][nt & 1], bh[nt >> 1][(nt & 1) + 2]);
                    mma16816(acc[mt][nt], a[mt], bl[nt >> 1][nt & 1], bl[nt >> 1][(nt & 1) + 2]);
                }
#pragma unroll
            for (int mt = 0; mt < 4; mt++) {
                int r = wm + mt * 16 + lr;
                ldsm4(a[mt], sb + 16384 + r * 128 + ((segk ^ (r & 7)) << 4));
            }
#pragma unroll
            for (int mt = 0; mt < 4; mt++)
#pragma unroll
                for (int nt = 0; nt < 4; nt++)
                    mma16816(acc[mt][nt], a[mt], bh[nt >> 1][nt & 1], bh[nt >> 1][(nt & 1) + 2]);
        }
        __syncthreads();
    }
    float* sf = (float*)smem;
    int g = lane >> 2, tq = lane & 3;
#pragma unroll
    for (int mt = 0; mt < 4; mt++)
#pragma unroll
        for (int nt = 0; nt < 4; nt++) {
            int r0 = wm + mt * 16 + g, c0 = wn + nt * 8 + tq * 2;
            sf[r0 * 129 + c0]           = acc[mt][nt][0];
            sf[r0 * 129 + c0 + 1]       = acc[mt][nt][1];
            sf[(r0 + 8) * 129 + c0]     = acc[mt][nt][2];
            sf[(r0 + 8) * 129 + c0 + 1] = acc[mt][nt][3];
        }
    __syncthreads();
    size_t gm0 = (size_t)bm * 128;
    int nc0 = bn * 128;
    for (int it = tid; it < 128 * 128; it += 256) {
        int r = it >> 7, col = it & 127;
        C[(gm0 + r) * 256 + nc0 + col] = sf[r * 129 + col];
    }
}

// -------- gather-based A_tot @ X --------
template <int L>
__global__ void k_spmm_gather(const float* __restrict__ alphap) {
    int gw = (blockIdx.x * 256 + threadIdx.x) >> 5, lane = threadIdx.x & 31;
    if (gw >= NN) return;
    const float* X = (L == 0) ? d_xw : d_hw;
    float* out = (L == 0) ? d_h1 : d_emb;
    float alpha = *alphap;
    float di = d_dinv[gw];
    const float4* xr = (const float4*)(X + (size_t)gw * 256);
    float4 x0 = xr[lane], x1 = xr[lane + 32];
    float sc = di * di;
    float4 a0 = make_float4(sc*x0.x, sc*x0.y, sc*x0.z, sc*x0.w);
    float4 a1 = make_float4(sc*x1.x, sc*x1.y, sc*x1.z, sc*x1.w);
    int b = d_rptr[gw], e = d_rptr[gw + 1];
    int p = b;
    for (; p + 1 < e; p += 2) {
        float w0 = d_cw[p], w1 = d_cw[p + 1];
        const float4* s0 = (const float4*)(X + (size_t)d_csrc[p] * 256);
        const float4* s1 = (const float4*)(X + (size_t)d_csrc[p + 1] * 256);
        float4 v00 = s0[lane], v01 = s0[lane + 32];
        float4 v10 = s1[lane], v11 = s1[lane + 32];
        fma4(a0, w0, v00); fma4(a1, w0, v01);
        fma4(a0, w1, v10); fma4(a1, w1, v11);
    }
    if (p < e) {
        float wv = d_cw[p];
        const float4* xs = (const float4*)(X + (size_t)d_csrc[p] * 256);
        fma4(a0, wv, xs[lane]); fma4(a1, wv, xs[lane + 32]);
    }
    a0.x*=alpha; a0.y*=alpha; a0.z*=alpha; a0.w*=alpha;
    a1.x*=alpha; a1.y*=alpha; a1.z*=alpha; a1.w*=alpha;
    int kb = d_kptr[gw], ke = d_kptr[gw + 1];
    p = kb;
    for (; p + 1 < ke; p += 2) {
        float w0 = d_kval[p], w1 = d_kval[p + 1];
        const float4* s0 = (const float4*)(X + (size_t)d_kidx[p] * 256);
        const float4* s1 = (const float4*)(X + (size_t)d_kidx[p + 1] * 256);
        float4 v00 = s0[lane], v01 = s0[lane + 32];
        float4 v10 = s1[lane], v11 = s1[lane + 32];
        fma4(a0, w0, v00); fma4(a1, w0, v01);
        fma4(a0, w1, v10); fma4(a1, w1, v11);
    }
    if (p < ke) {
        float v = d_kval[p];
        const float4* xs = (const float4*)(X + (size_t)d_kidx[p] * 256);
        fma4(a0, v, xs[lane]); fma4(a1, v, xs[lane + 32]);
    }
    if (L == 0) {
        a0.x=fmaxf(a0.x,0.f); a0.y=fmaxf(a0.y,0.f); a0.z=fmaxf(a0.z,0.f); a0.w=fmaxf(a0.w,0.f);
        a1.x=fmaxf(a1.x,0.f); a1.y=fmaxf(a1.y,0.f); a1.z=fmaxf(a1.z,0.f); a1.w=fmaxf(a1.w,0.f);
        // hi/lo split of h1 for the next bf16 GEMM
        int c0 = lane * 4;
        float vs0[4] = {a0.x, a0.y, a0.z, a0.w};
        float vs1[4] = {a1.x, a1.y, a1.z, a1.w};
#pragma unroll
        for (int u = 0; u < 4; u++) {
            __nv_bfloat16 h0 = __float2bfloat16(vs0[u]);
            d_h1h[(size_t)gw * 256 + c0 + u] = h0;
            d_h1l[(size_t)gw * 256 + c0 + u] = __float2bfloat16(vs0[u] - __bfloat162float(h0));
            __nv_bfloat16 h1v = __float2bfloat16(vs1[u]);
            d_h1h[(size_t)gw * 256 + 128 + c0 + u] = h1v;
            d_h1l[(size_t)gw * 256 + 128 + c0 + u] = __float2bfloat16(vs1[u] - __bfloat162float(h1v));
        }
    }
    float4* orow = (float4*)(out + (size_t)gw * 256);
    orow[lane] = a0; orow[lane + 32] = a1;
}

// -------- classification --------
__global__ void k_cls_scatter(const int* __restrict__ labels, const int* __restrict__ nidx) {
    int w = (blockIdx.x*256+threadIdx.x) >> 5, lane = threadIdx.x & 31;
    if (w >= NSEL) return;
    int lbl = labels[w];
    const float4* er = (const float4*)(d_emb + (size_t)nidx[w]*HIDD);
    float4* sr = (float4*)(d_sums + lbl*HIDD);
#pragma unroll
    for (int q = 0; q < 2; q++) {
        int f = lane + 32*q; float4 v = er[f];
        red4(&sr[f], v.x, v.y, v.z, v.w);
    }
    if (lane == 0) atomicAdd(&d_cnt[lbl], 1.f);
}
__global__ void k_proto() {
    int c = blockIdx.x, t = threadIdx.x;
    float cnt = d_cnt[c];
    float sm = d_sums[c*HIDD+t];
    float p = sm / fmaxf(cnt, 1.f);
    __shared__ float red[256];
    red[t] = p*p;
    __syncthreads();
    for (int s = 128; s > 0; s >>= 1) { if (t < s) red[t] += red[t+s]; __syncthreads(); }
    d_pn[c*HIDD+t] = p / (sqrtf(red[0]) + EPSF);
    d_sums[c*HIDD+t] = 0.f;
    if (t == 0) d_cnt[c] = 0.f;
}
__global__ void k_out(const int* __restrict__ nidx, float* __restrict__ out) {
    int w = (blockIdx.x*256+threadIdx.x) >> 5, lane = threadIdx.x & 31;
    if (w >= NSEL) return;
    const float* er = d_emb + (size_t)nidx[w]*HIDD;
    float v[8]; float ss = 0.f;
#pragma unroll
    for (int q = 0; q < 8; q++) { v[q] = er[lane+32*q]; ss += v[q]*v[q]; }
    ss = warp_sum(ss);
    float rn = 1.f / (sqrtf(ss) + EPSF);
#pragma unroll
    for (int c = 0; c < NCLS; c++) {
        float dp = 0.f;
#pragma unroll
        for (int q = 0; q < 8; q++) dp += v[q] * d_pn[c*HIDD + lane + 32*q];
        dp = warp_sum(dp);
        if (lane == 0) out[w*NCLS + c] = dp * rn * 5.0f;
    }
}

extern "C" void kernel_launch(void* const* d_in, const int* in_sizes, int n_in,
                              void* d_out, int out_size) {
    const float* x   = (const float*)d_in[0];
    const float* cw  = (const float*)d_in[1];
    const float* alp = (const float*)d_in[2];
    const float* ps  = (const float*)d_in[3];
    const float* st  = (const float*)d_in[4];
    const float* bal = (const float*)d_in[5];
    const float* W1  = (const float*)d_in[6];
    const float* W2  = (const float*)d_in[7];
    const int*   ei  = (const int*)d_in[8];
    const int*   lab = (const int*)d_in[9];
    const int*   nix = (const int*)d_in[10];
    float* out = (float*)d_out;
    const int* esrc = ei;
    const int* edst = ei + NE;

    cudaFuncSetAttribute(k_mma_sims, cudaFuncAttributeMaxDynamicSharedMemorySize, SIMS_SMEM);
    cudaFuncSetAttribute(k_gemm_bf16<0>, cudaFuncAttributeMaxDynamicSharedMemorySize, SIMS_SMEM);
    cudaFuncSetAttribute(k_gemm_bf16<1>, cudaFuncAttributeMaxDynamicSharedMemorySize, SIMS_SMEM);

    k_wpack<<<512, 256>>>(W1, W2);
    k_fea<<<NN*FIN/256, 256>>>(x, cw, ps, st, edst);
    k_scan<<<1, 256>>>();
    k_fill<<<NE/256, 256>>>(esrc, edst);
    k_agg_h<<<NN/8, 256>>>(bal);
    k_mma_sims<<<2080, 256, SIMS_SMEM>>>();
    k_topk<<<NN, 256>>>(alp);
    k_kcount<<<NN*KT/8, 256>>>();
    k_kscan<<<1, 256>>>();
    k_kfill<<<(NN*KT+255)/256, 256>>>();

    k_gemm_bf16<0><<<dim3(2, 64), 256, SIMS_SMEM>>>();
    k_spmm_gather<0><<<NN/8, 256>>>(alp);
    k_gemm_bf16<1><<<dim3(2, 64), 256, SIMS_SMEM>>>();
    k_spmm_gather<1><<<NN/8, 256>>>(alp);

    k_cls_scatter<<<NSEL/8, 256>>>(lab, nix);
    k_proto<<<NCLS, 256>>>();
    k_out<<<NSEL/8, 256>>>(nix, out);
}

// round 11
// speedup vs baseline: 2.8394x; 1.0110x over previous
#include <cuda_runtime.h>
#include <cuda_bf16.h>
#include <math.h>
#include <float.h>
#include <stdint.h>

#define NN   8192
#define FIN  256
#define HIDD 256
#define NE   131072
#define KT   17
#define CANDCAP 96
#define NCLS 10
#define NSEL 4096
#define EPSF 1e-8f

__device__ __align__(16) float d_fea[NN * FIN];
__device__ __align__(16) __nv_bfloat16 d_feah[NN * FIN];
__device__ __align__(16) __nv_bfloat16 d_feal[NN * FIN];
__device__ float d_dinv[NN];
__device__ int   d_cnt_e[NN];          // self-clean in k_scan
__device__ int   d_rptr[NN + 1];
__device__ int   d_cur[NN];
__device__ int   d_csrc[NE];
__device__ float d_cw[NE];
__device__ __align__(16) float d_hn[NN * 512];
__device__ __align__(16) __nv_bfloat16 d_hb[NN * 512];
__device__ __nv_bfloat16 d_simh[(size_t)NN * NN];
__device__ int   d_tidx[NN * KT];
__device__ float d_tval[NN * KT];
__device__ int   d_kcnt[NN];           // self-clean in k_kscan
__device__ int   d_kptr[NN + 1];
__device__ int   d_kcur[NN];
__device__ unsigned char d_kmut[NN * KT];
__device__ int   d_kidx[NN * KT * 2];
__device__ float d_kval[NN * KT * 2];
__device__ __align__(16) __nv_bfloat16 d_w1h[FIN * HIDD];
__device__ __align__(16) __nv_bfloat16 d_w1l[FIN * HIDD];
__device__ __align__(16) __nv_bfloat16 d_w2h[HIDD * HIDD];
__device__ __align__(16) __nv_bfloat16 d_w2l[HIDD * HIDD];
__device__ __align__(16) float d_xw[NN * HIDD];
__device__ __align__(16) float d_h1[NN * HIDD];
__device__ __align__(16) __nv_bfloat16 d_h1h[NN * HIDD];
__device__ __align__(16) __nv_bfloat16 d_h1l[NN * HIDD];
__device__ __align__(16) float d_hw[NN * HIDD];
__device__ __align__(16) float d_emb[NN * HIDD];
__device__ __align__(16) float d_sums[NCLS * HIDD]; // self-clean in k_proto
__device__ float d_cnt[NCLS];                       // self-clean in k_proto
__device__ float d_pn[NCLS * HIDD];

__device__ __forceinline__ float warp_sum(float v) {
#pragma unroll
    for (int o = 16; o > 0; o >>= 1) v += __shfl_xor_sync(0xffffffffu, v, o);
    return v;
}
__device__ __forceinline__ void red4(float4* addr, float a, float b, float c, float d) {
    asm volatile("red.global.add.v4.f32 [%0], {%1,%2,%3,%4};"
                 :: "l"(addr), "f"(a), "f"(b), "f"(c), "f"(d) : "memory");
}
__device__ __forceinline__ void fma4(float4& a, float w, const float4 v) {
    a.x += w * v.x; a.y += w * v.y; a.z += w * v.z; a.w += w * v.w;
}
__device__ __forceinline__ uint2 pack_bf16x4(float4 v) {
    __nv_bfloat162 lo = __floats2bfloat162_rn(v.x, v.y);
    __nv_bfloat162 hi = __floats2bfloat162_rn(v.z, v.w);
    uint2 r;
    r.x = *reinterpret_cast<uint32_t*>(&lo);
    r.y = *reinterpret_cast<uint32_t*>(&hi);
    return r;
}
__device__ __forceinline__ uint32_t bf16key(uint32_t b) {  // monotone 16-bit key
    return (b & 0x8000u) ? (~b & 0xFFFFu) : (b | 0x8000u);
}

// -------- fea = elu(...) + hi/lo split + degree count + fused wpack --------
__global__ void k_fea(const float* __restrict__ x, const float* __restrict__ cw,
                      const float* __restrict__ ps, const float* __restrict__ st,
                      const int* __restrict__ dst,
                      const float* __restrict__ W1, const float* __restrict__ W2) {
    int idx = blockIdx.x * 256 + threadIdx.x;
    int f = idx & (FIN - 1);
    float z = x[idx] * (cw[0] * ps[f] + cw[1] * st[f]);
    float r = z > 0.f ? z : expm1f(z);
    d_fea[idx] = r;
    __nv_bfloat16 hi = __float2bfloat16(r);
    d_feah[idx] = hi;
    d_feal[idx] = __float2bfloat16(r - __bfloat162float(hi));
    if (idx < NE) {
        atomicAdd(&d_cnt_e[dst[idx]], 1);
        // fused weight transpose + split
        int wsel = idx >> 16;
        int e = idx & 0xFFFF;
        int k = e >> 8, n = e & 255;
        float v = (wsel ? W2 : W1)[e];
        __nv_bfloat16 wh = __float2bfloat16(v);
        __nv_bfloat16 wl = __float2bfloat16(v - __bfloat162float(wh));
        (wsel ? d_w2h : d_w1h)[n * 256 + k] = wh;
        (wsel ? d_w2l : d_w1l)[n * 256 + k] = wl;
    }
}
// -------- scan (+self-clean counts) --------
__global__ void k_scan() {
    __shared__ int bs[256];
    int t = threadIdx.x;
    int loc[32]; int s = 0;
#pragma unroll
    for (int q = 0; q < 32; q++) {
        loc[q] = d_cnt_e[t * 32 + q];
        d_cnt_e[t * 32 + q] = 0;
        s += loc[q];
    }
    bs[t] = s; __syncthreads();
    for (int off = 1; off < 256; off <<= 1) {
        int v = (t >= off) ? bs[t - off] : 0;
        __syncthreads();
        bs[t] += v;
        __syncthreads();
    }
    int run = bs[t] - s;
#pragma unroll
    for (int q = 0; q < 32; q++) {
        int i = t * 32 + q;
        d_rptr[i] = run; d_cur[i] = run;
        d_dinv[i] = rsqrtf((float)(loc[q] + 1));
        run += loc[q];
    }
    if (t == 255) d_rptr[NN] = run;
}
__global__ void k_fill(const int* __restrict__ src, const int* __restrict__ dst) {
    int e = blockIdx.x * 256 + threadIdx.x;
    if (e >= NE) return;
    int s = src[e], d = dst[e];
    int pos = atomicAdd(&d_cur[d], 1);
    d_csrc[pos] = s;
    d_cw[pos] = d_dinv[s] * d_dinv[d];
}
// -------- fused aggregate-gather + h-normalize + bf16 --------
__global__ void k_agg_h(const float* __restrict__ bal) {
    int gw = (blockIdx.x * 256 + threadIdx.x) >> 5, lane = threadIdx.x & 31;
    if (gw >= NN) return;
    float di = d_dinv[gw];
    const float4* fr = (const float4*)(d_fea + (size_t)gw * 256);
    float4 f0 = fr[lane], f1 = fr[lane + 32];
    float sc = di * di;
    float4 a0 = make_float4(sc*f0.x, sc*f0.y, sc*f0.z, sc*f0.w);
    float4 a1 = make_float4(sc*f1.x, sc*f1.y, sc*f1.z, sc*f1.w);
    int b = d_rptr[gw], e = d_rptr[gw + 1];
    int p = b;
    for (; p + 1 < e; p += 2) {
        float w0 = d_cw[p], w1 = d_cw[p + 1];
        const float4* s0 = (const float4*)(d_fea + (size_t)d_csrc[p] * 256);
        const float4* s1 = (const float4*)(d_fea + (size_t)d_csrc[p + 1] * 256);
        float4 v00 = s0[lane], v01 = s0[lane + 32];
        float4 v10 = s1[lane], v11 = s1[lane + 32];
        fma4(a0, w0, v00); fma4(a1, w0, v01);
        fma4(a0, w1, v10); fma4(a1, w1, v11);
    }
    if (p < e) {
        float wv = d_cw[p];
        const float4* fs = (const float4*)(d_fea + (size_t)d_csrc[p] * 256);
        fma4(a0, wv, fs[lane]); fma4(a1, wv, fs[lane + 32]);
    }
    const float4* bb = (const float4*)bal;
    float4 bA = bb[lane], bB = bb[lane + 32], bC = bb[64 + lane], bD = bb[96 + lane];
    float4 hA = make_float4(f0.x*bA.x, f0.y*bA.y, f0.z*bA.z, f0.w*bA.w);
    float4 hB = make_float4(f1.x*bB.x, f1.y*bB.y, f1.z*bB.z, f1.w*bB.w);
    float4 hC = make_float4(a0.x*bC.x, a0.y*bC.y, a0.z*bC.z, a0.w*bC.w);
    float4 hD = make_float4(a1.x*bD.x, a1.y*bD.y, a1.z*bD.z, a1.w*bD.w);
    float ss = hA.x*hA.x+hA.y*hA.y+hA.z*hA.z+hA.w*hA.w
             + hB.x*hB.x+hB.y*hB.y+hB.z*hB.z+hB.w*hB.w
             + hC.x*hC.x+hC.y*hC.y+hC.z*hC.z+hC.w*hC.w
             + hD.x*hD.x+hD.y*hD.y+hD.z*hD.z+hD.w*hD.w;
    ss = warp_sum(ss);
    float rn = 1.f / (sqrtf(ss) + EPSF);
    hA.x*=rn; hA.y*=rn; hA.z*=rn; hA.w*=rn;
    hB.x*=rn; hB.y*=rn; hB.z*=rn; hB.w*=rn;
    hC.x*=rn; hC.y*=rn; hC.z*=rn; hC.w*=rn;
    hD.x*=rn; hD.y*=rn; hD.z*=rn; hD.w*=rn;
    float4* hr = (float4*)(d_hn + (size_t)gw * 512);
    hr[lane] = hA; hr[lane + 32] = hB; hr[64 + lane] = hC; hr[96 + lane] = hD;
    uint2* hb = (uint2*)(d_hb + (size_t)gw * 512);
    hb[lane] = pack_bf16x4(hA); hb[lane + 32] = pack_bf16x4(hB);
    hb[64 + lane] = pack_bf16x4(hC); hb[96 + lane] = pack_bf16x4(hD);
}

// ======== mma helpers ========
__device__ __forceinline__ uint32_t smem_u32(const void* p) {
    uint32_t a;
    asm("{ .reg .u64 t; cvta.to.shared.u64 t, %1; cvt.u32.u64 %0, t; }" : "=r"(a) : "l"(p));
    return a;
}
__device__ __forceinline__ void ldsm4(uint32_t* r, uint32_t addr) {
    asm volatile("ldmatrix.sync.aligned.m8n8.x4.shared.b16 {%0,%1,%2,%3}, [%4];"
                 : "=r"(r[0]), "=r"(r[1]), "=r"(r[2]), "=r"(r[3]) : "r"(addr));
}
__device__ __forceinline__ void mma16816(float* c, const uint32_t* a, uint32_t b0, uint32_t b1) {
    asm volatile("mma.sync.aligned.m16n8k16.row.col.f32.bf16.bf16.f32 "
                 "{%0,%1,%2,%3}, {%4,%5,%6,%7}, {%8,%9}, {%0,%1,%2,%3};"
                 : "+f"(c[0]), "+f"(c[1]), "+f"(c[2]), "+f"(c[3])
                 : "r"(a[0]), "r"(a[1]), "r"(a[2]), "r"(a[3]), "r"(b0), "r"(b1));
}
// A 128x64 + B 128x64 stage load, 128 threads
__device__ __forceinline__ void sims_load(uint32_t sbase, const __nv_bfloat16* Ag,
                                          const __nv_bfloat16* Bg, int c, int tid) {
#pragma unroll
    for (int q = 0; q < 16; q++) {
        int seg = tid + 128 * q;                 // 0..2047
        int h = seg >> 10;                       // 0: A, 1: B
        int rs = seg & 1023;
        int r = rs >> 3, s8 = rs & 7;
        uint32_t dst = sbase + (uint32_t)h * 16384 + r * 128 + ((s8 ^ (r & 7)) << 4);
        const __nv_bfloat16* G = h ? Bg : Ag;
        const char* src = (const char*)(G + (size_t)r * 512 + c * 64 + s8 * 8);
        asm volatile("cp.async.cg.shared.global [%0], [%1], 16;"
                     :: "r"(dst), "l"(src) : "memory");
    }
    asm volatile("cp.async.commit_group;" ::: "memory");
}
// 128 rows x 64 bf16 tile from a row-stride-256 matrix (256 threads)
__device__ __forceinline__ void gload(uint32_t dst_base, const __nv_bfloat16* G,
                                      int k0, int tid) {
#pragma unroll
    for (int q = 0; q < 4; q++) {
        int seg = tid + 256 * q;
        int r = seg >> 3, s8 = seg & 7;
        uint32_t dst = dst_base + r * 128 + ((s8 ^ (r & 7)) << 4);
        const char* src = (const char*)(G + (size_t)r * 256 + k0 + s8 * 8);
        asm volatile("cp.async.cg.shared.global [%0], [%1], 16;"
                     :: "r"(dst), "l"(src) : "memory");
    }
}
#define SIMS_SMEM 66048

// ======== sims: 128 threads, 4 warps x (64x64) tiles ========
__global__ void __launch_bounds__(128, 2) k_mma_sims() {
    int idx = blockIdx.x;
    int bj = (int)((sqrtf(8.f * idx + 1.f) - 1.f) * 0.5f);
    while ((bj + 1) * (bj + 2) / 2 <= idx) bj++;
    while (bj * (bj + 1) / 2 > idx) bj--;
    int bi = idx - bj * (bj + 1) / 2;           // bi <= bj
    extern __shared__ char smem[];
    uint32_t sb = smem_u32(smem);
    int tid = threadIdx.x;
    int lane = tid & 31, w = tid >> 5;          // 4 warps
    int wm = (w & 1) * 64, wn = (w >> 1) * 64;

    const __nv_bfloat16* Ag = d_hb + (size_t)bi * 128 * 512;
    const __nv_bfloat16* Bg = d_hb + (size_t)bj * 128 * 512;

    float acc[4][8][4];
#pragma unroll
    for (int mt = 0; mt < 4; mt++)
#pragma unroll
        for (int nt = 0; nt < 8; nt++)
#pragma unroll
            for (int e = 0; e < 4; e++) acc[mt][nt][e] = 0.f;

    sims_load(sb, Ag, Bg, 0, tid);
    int lr = lane & 15, lks = lane >> 4;
    for (int c = 0; c < 8; c++) {
        if (c < 7) sims_load(sb + ((c + 1) & 1) * 32768, Ag, Bg, c + 1, tid);
        if (c < 7) asm volatile("cp.async.wait_group 1;" ::: "memory");
        else       asm volatile("cp.async.wait_group 0;" ::: "memory");
        __syncthreads();
        uint32_t aB = sb + (c & 1) * 32768, bB = aB + 16384;
#pragma unroll
        for (int ks = 0; ks < 4; ks++) {
            int segk = ks * 2 + lks;
            uint32_t a[4][4], b[4][4];
#pragma unroll
            for (int mt = 0; mt < 4; mt++) {
                int r = wm + mt * 16 + lr;
                ldsm4(a[mt], aB + r * 128 + ((segk ^ (r & 7)) << 4));
            }
#pragma unroll
            for (int bt = 0; bt < 4; bt++) {
                int r = wn + bt * 16 + lr;
                ldsm4(b[bt], bB + r * 128 + ((segk ^ (r & 7)) << 4));
            }
#pragma unroll
            for (int mt = 0; mt < 4; mt++)
#pragma unroll
                for (int nt = 0; nt < 8; nt++)
                    mma16816(acc[mt][nt], a[mt], b[nt >> 1][nt & 1], b[nt >> 1][(nt & 1) + 2]);
        }
        __syncthreads();
    }
    float* sf = (float*)smem;
    int g = lane >> 2, tq = lane & 3;
#pragma unroll
    for (int mt = 0; mt < 4; mt++)
#pragma unroll
        for (int nt = 0; nt < 8; nt++) {
            int r0 = wm + mt * 16 + g, c0 = wn + nt * 8 + tq * 2;
            sf[r0 * 129 + c0]           = acc[mt][nt][0];
            sf[r0 * 129 + c0 + 1]       = acc[mt][nt][1];
            sf[(r0 + 8) * 129 + c0]     = acc[mt][nt][2];
            sf[(r0 + 8) * 129 + c0 + 1] = acc[mt][nt][3];
        }
    __syncthreads();
    size_t gi0 = (size_t)bi * 128, gj0 = (size_t)bj * 128;
    if (bi != bj) {
        for (int it = tid; it < 128 * 64; it += 128) {
            int r = it >> 6, c2 = (it & 63) * 2;
            __nv_bfloat162 p = __floats2bfloat162_rn(sf[r * 129 + c2], sf[r * 129 + c2 + 1]);
            *(__nv_bfloat162*)&d_simh[(gi0 + r) * NN + gj0 + c2] = p;
        }
        for (int it = tid; it < 128 * 64; it += 128) {
            int j = it >> 6, i2 = (it & 63) * 2;
            __nv_bfloat162 p = __floats2bfloat162_rn(sf[i2 * 129 + j], sf[(i2 + 1) * 129 + j]);
            *(__nv_bfloat162*)&d_simh[(gj0 + j) * NN + gi0 + i2] = p;
        }
    } else {
        for (int it = tid; it < 128 * 64; it += 128) {
            int r = it >> 6, c2 = (it & 63) * 2;
            float v0 = (c2 >= r)     ? sf[r * 129 + c2]     : sf[c2 * 129 + r];
            float v1 = (c2 + 1 >= r) ? sf[r * 129 + c2 + 1] : sf[(c2 + 1) * 129 + r];
            __nv_bfloat162 p = __floats2bfloat162_rn(v0, v1);
            *(__nv_bfloat162*)&d_simh[(gi0 + r) * NN + gj0 + c2] = p;
        }
    }
}

// -------- topk: max-relative bins + prefilter + exact rescore --------
__global__ void k_topk(const float* __restrict__ alphap) {
    int row = blockIdx.x, t = threadIdx.x;
    int w = t >> 5, lane = t & 31;
    const uint4* srow = (const uint4*)(d_simh + (size_t)row * NN);  // 1024 uint4
    uint32_t kp[16];
#pragma unroll
    for (int q = 0; q < 4; q++) {
        uint4 r4 = srow[q * 256 + t];
        uint32_t rr[4] = {r4.x, r4.y, r4.z, r4.w};
#pragma unroll
        for (int u = 0; u < 4; u++)
            kp[q * 4 + u] = bf16key(rr[u] & 0xFFFFu) | (bf16key(rr[u] >> 16) << 16);
    }
    __shared__ int hist[256];
    __shared__ int scn[256];
    __shared__ uint32_t sMax[8];
    __shared__ int sB, cnum;
    __shared__ int   cand[CANDCAP];
    __shared__ float cex[CANDCAP];
    hist[t] = 0;
    if (t == 0) { cnum = 0; sB = 255; }
    uint32_t mk = 0;
#pragma unroll
    for (int q = 0; q < 16; q++) {
        uint32_t a = kp[q] & 0xFFFFu, b2 = kp[q] >> 16;
        mk = max(mk, max(a, b2));
    }
#pragma unroll
    for (int o = 16; o > 0; o >>= 1)
        mk = max(mk, __shfl_xor_sync(0xffffffffu, mk, o));
    if (lane == 0) sMax[w] = mk;
    __syncthreads();
    uint32_t Kmax = sMax[0];
#pragma unroll
    for (int q = 1; q < 8; q++) Kmax = max(Kmax, sMax[q]);
#pragma unroll
    for (int q = 0; q < 16; q++) {
        uint32_t d0 = (Kmax - (kp[q] & 0xFFFFu)) >> 2;
        uint32_t d1 = (Kmax - (kp[q] >> 16)) >> 2;
        if (d0 < 256) atomicAdd(&hist[d0], 1);
        if (d1 < 256) atomicAdd(&hist[d1], 1);
    }
    __syncthreads();
    int hv = hist[t];
    scn[t] = hv;
    __syncthreads();
    for (int off = 1; off < 256; off <<= 1) {
        int v = (t >= off) ? scn[t - off] : 0;
        __syncthreads();
        scn[t] += v;
        __syncthreads();
    }
    if (scn[t] >= 32 && scn[t] - hv < 32) sB = t;
    __syncthreads();
    int B = sB;
    // compaction: lane's u32 q covers columns {q*512 + 2t, +1} (uint4 layout: q = qq*4+u -> col base)
#pragma unroll
    for (int q = 0; q < 16; q++) {
        uint32_t d0 = (Kmax - (kp[q] & 0xFFFFu)) >> 2;
        uint32_t d1 = (Kmax - (kp[q] >> 16)) >> 2;
        int qq = q >> 2, u = q & 3;
        int colbase = qq * 2048 + t * 8 + u * 2;
        if ((int)d0 <= B) { int pos = atomicAdd(&cnum, 1); if (pos < CANDCAP) cand[pos] = colbase; }
        if ((int)d1 <= B) { int pos = atomicAdd(&cnum, 1); if (pos < CANDCAP) cand[pos] = colbase + 1; }
    }
    __syncthreads();
    int nc = min(cnum, CANDCAP);
    const float* hr = d_hn + (size_t)row * 512;
    for (int c = w; c < nc; c += 8) {
        const float* hj = d_hn + (size_t)cand[c] * 512;
        float s = 0.f;
#pragma unroll
        for (int e = 0; e < 16; e++) s += hr[lane + e * 32] * hj[lane + e * 32];
        s = warp_sum(s);
        if (lane == 0) cex[c] = s;
    }
    __syncthreads();
    if (t < nc) {
        float myv = cex[t]; int myi = cand[t];
        int rank = 0;
        for (int c = 0; c < nc; c++) {
            float v = cex[c]; int ci = cand[c];
            if (v > myv || (v == myv && ci < myi)) rank++;
        }
        if (rank < KT) {
            d_tidx[row * KT + rank] = myi;
            d_tval[row * KT + rank] = (1.f - *alphap) * fmaxf(myv, 0.f);
        }
    }
}

// -------- kNN symmetric CSR build --------
__global__ void k_kcount() {
    int w = (blockIdx.x * 256 + threadIdx.x) >> 5, lane = threadIdx.x & 31;
    if (w >= NN * KT) return;
    int i = w / KT, j = d_tidx[w];
    int cand = (lane < KT) ? d_tidx[j * KT + lane] : -1;
    unsigned f = __ballot_sync(0xffffffffu, cand == i);
    if (lane == 0) {
        atomicAdd(&d_kcnt[i], 1);
        d_kmut[w] = (f != 0);
        if (!f) atomicAdd(&d_kcnt[j], 1);
    }
}
__global__ void k_kscan() {
    __shared__ int bs[256];
    int t = threadIdx.x;
    int loc[32]; int s = 0;
#pragma unroll
    for (int q = 0; q < 32; q++) {
        loc[q] = d_kcnt[t * 32 + q];
        d_kcnt[t * 32 + q] = 0;
        s += loc[q];
    }
    bs[t] = s; __syncthreads();
    for (int off = 1; off < 256; off <<= 1) {
        int v = (t >= off) ? bs[t - off] : 0;
        __syncthreads();
        bs[t] += v;
        __syncthreads();
    }
    int run = bs[t] - s;
#pragma unroll
    for (int q = 0; q < 32; q++) {
        int i = t * 32 + q;
        d_kptr[i] = run; d_kcur[i] = run;
        run += loc[q];
    }
    if (t == 255) d_kptr[NN] = run;
}
__global__ void k_kfill() {
    int w = blockIdx.x * 256 + threadIdx.x;
    if (w >= NN * KT) return;
    int i = w / KT, j = d_tidx[w];
    float v = d_tval[w];
    int pos = atomicAdd(&d_kcur[i], 1);
    d_kidx[pos] = j; d_kval[pos] = v;
    if (!d_kmut[w]) {
        int pos2 = atomicAdd(&d_kcur[j], 1);
        d_kidx[pos2] = i; d_kval[pos2] = v;
    }
}

// -------- bf16 split GEMM: C[8192,256] = A @ W (3-term hi/lo) --------
template <int L>
__global__ void __launch_bounds__(256) k_gemm_bf16() {
    int bn = blockIdx.x, bm = blockIdx.y;
    extern __shared__ char smem[];
    uint32_t sb = smem_u32(smem);
    int tid = threadIdx.x, lane = tid & 31, w = tid >> 5;
    int wm = (w & 1) * 64, wn = (w >> 1) * 32;
    const __nv_bfloat16* Ah = (L ? d_h1h : d_feah) + (size_t)bm * 128 * 256;
    const __nv_bfloat16* Al = (L ? d_h1l : d_feal) + (size_t)bm * 128 * 256;
    const __nv_bfloat16* Bh = (L ? d_w2h : d_w1h) + (size_t)bn * 128 * 256;
    const __nv_bfloat16* Bl = (L ? d_w2l : d_w1l) + (size_t)bn * 128 * 256;
    float* C = L ? d_hw : d_xw;

    float acc[4][4][4];
#pragma unroll
    for (int mt = 0; mt < 4; mt++)
#pragma unroll
        for (int nt = 0; nt < 4; nt++)
#pragma unroll
            for (int e = 0; e < 4; e++) acc[mt][nt][e] = 0.f;

    int lr = lane & 15, lks = lane >> 4;
    for (int c = 0; c < 4; c++) {
        int k0 = c * 64;
        gload(sb,         Ah, k0, tid);
        gload(sb + 16384, Al, k0, tid);
        gload(sb + 32768, Bh, k0, tid);
        gload(sb + 49152, Bl, k0, tid);
        asm volatile("cp.async.commit_group;" ::: "memory");
        asm volatile("cp.async.wait_group 0;" ::: "memory");
        __syncthreads();
#pragma unroll
        for (int ks = 0; ks < 4; ks++) {
            int segk = ks * 2 + lks;
            uint32_t a[4][4], bh[2][4], bl[2][4];
#pragma unroll
            for (int bt = 0; bt < 2; bt++) {
                int r = wn + bt * 16 + lr;
                uint32_t off = r * 128 + ((segk ^ (r & 7)) << 4);
                ldsm4(bh[bt], sb + 32768 + off);
                ldsm4(bl[bt], sb + 49152 + off);
            }
#pragma unroll
            for (int mt = 0; mt < 4; mt++) {
                int r = wm + mt * 16 + lr;
                ldsm4(a[mt], sb + r * 128 + ((segk ^ (r & 7)) << 4));
            }
#pragma unroll
            for (int mt = 0; mt < 4; mt++)
#pragma unroll
                for (int nt = 0; nt < 4; nt++) {
                    mma16816(acc[mt][nt], a[mt], bh[nt >> 1][nt & 1], bh[nt >> 1][(nt & 1) + 2]);
                    mma16816(acc[mt][nt], a[mt], bl[nt >> 1][nt & 1], bl[nt >> 1][(nt & 1) + 2]);
                }
#pragma unroll
            for (int mt = 0; mt < 4; mt++) {
                int r = wm + mt * 16 + lr;
                ldsm4(a[mt], sb + 16384 + r * 128 + ((segk ^ (r & 7)) << 4));
            }
#pragma unroll
            for (int mt = 0; mt < 4; mt++)
#pragma unroll
                for (int nt = 0; nt < 4; nt++)
                    mma16816(acc[mt][nt], a[mt], bh[nt >> 1][nt & 1], bh[nt >> 1][(nt & 1) + 2]);
        }
        __syncthreads();
    }
    float* sf = (float*)smem;
    int g = lane >> 2, tq = lane & 3;
#pragma unroll
    for (int mt = 0; mt < 4; mt++)
#pragma unroll
        for (int nt = 0; nt < 4; nt++) {
            int r0 = wm + mt * 16 + g, c0 = wn + nt * 8 + tq * 2;
            sf[r0 * 129 + c0]           = acc[mt][nt][0];
            sf[r0 * 129 + c0 + 1]       = acc[mt][nt][1];
            sf[(r0 + 8) * 129 + c0]     = acc[mt][nt][2];
            sf[(r0 + 8) * 129 + c0 + 1] = acc[mt][nt][3];
        }
    __syncthreads();
    size_t gm0 = (size_t)bm * 128;
    int nc0 = bn * 128;
    for (int it = tid; it < 128 * 128; it += 256) {
        int r = it >> 7, col = it & 127;
        C[(gm0 + r) * 256 + nc0 + col] = sf[r * 129 + col];
    }
}

// -------- gather-based A_tot @ X --------
template <int L>
__global__ void k_spmm_gather(const float* __restrict__ alphap) {
    int gw = (blockIdx.x * 256 + threadIdx.x) >> 5, lane = threadIdx.x & 31;
    if (gw >= NN) return;
    const float* X = (L == 0) ? d_xw : d_hw;
    float* out = (L == 0) ? d_h1 : d_emb;
    float alpha = *alphap;
    float di = d_dinv[gw];
    const float4* xr = (const float4*)(X + (size_t)gw * 256);
    float4 x0 = xr[lane], x1 = xr[lane + 32];
    float sc = di * di;
    float4 a0 = make_float4(sc*x0.x, sc*x0.y, sc*x0.z, sc*x0.w);
    float4 a1 = make_float4(sc*x1.x, sc*x1.y, sc*x1.z, sc*x1.w);
    int b = d_rptr[gw], e = d_rptr[gw + 1];
    int p = b;
    for (; p + 1 < e; p += 2) {
        float w0 = d_cw[p], w1 = d_cw[p + 1];
        const float4* s0 = (const float4*)(X + (size_t)d_csrc[p] * 256);
        const float4* s1 = (const float4*)(X + (size_t)d_csrc[p + 1] * 256);
        float4 v00 = s0[lane], v01 = s0[lane + 32];
        float4 v10 = s1[lane], v11 = s1[lane + 32];
        fma4(a0, w0, v00); fma4(a1, w0, v01);
        fma4(a0, w1, v10); fma4(a1, w1, v11);
    }
    if (p < e) {
        float wv = d_cw[p];
        const float4* xs = (const float4*)(X + (size_t)d_csrc[p] * 256);
        fma4(a0, wv, xs[lane]); fma4(a1, wv, xs[lane + 32]);
    }
    a0.x*=alpha; a0.y*=alpha; a0.z*=alpha; a0.w*=alpha;
    a1.x*=alpha; a1.y*=alpha; a1.z*=alpha; a1.w*=alpha;
    int kb = d_kptr[gw], ke = d_kptr[gw + 1];
    p = kb;
    for (; p + 1 < ke; p += 2) {
        float w0 = d_kval[p], w1 = d_kval[p + 1];
        const float4* s0 = (const float4*)(X + (size_t)d_kidx[p] * 256);
        const float4* s1 = (const float4*)(X + (size_t)d_kidx[p + 1] * 256);
        float4 v00 = s0[lane], v01 = s0[lane + 32];
        float4 v10 = s1[lane], v11 = s1[lane + 32];
        fma4(a0, w0, v00); fma4(a1, w0, v01);
        fma4(a0, w1, v10); fma4(a1, w1, v11);
    }
    if (p < ke) {
        float v = d_kval[p];
        const float4* xs = (const float4*)(X + (size_t)d_kidx[p] * 256);
        fma4(a0, v, xs[lane]); fma4(a1, v, xs[lane + 32]);
    }
    if (L == 0) {
        a0.x=fmaxf(a0.x,0.f); a0.y=fmaxf(a0.y,0.f); a0.z=fmaxf(a0.z,0.f); a0.w=fmaxf(a0.w,0.f);
        a1.x=fmaxf(a1.x,0.f); a1.y=fmaxf(a1.y,0.f); a1.z=fmaxf(a1.z,0.f); a1.w=fmaxf(a1.w,0.f);
        int c0 = lane * 4;
        float vs0[4] = {a0.x, a0.y, a0.z, a0.w};
        float vs1[4] = {a1.x, a1.y, a1.z, a1.w};
#pragma unroll
        for (int u = 0; u < 4; u++) {
            __nv_bfloat16 h0 = __float2bfloat16(vs0[u]);
            d_h1h[(size_t)gw * 256 + c0 + u] = h0;
            d_h1l[(size_t)gw * 256 + c0 + u] = __float2bfloat16(vs0[u] - __bfloat162float(h0));
            __nv_bfloat16 h1v = __float2bfloat16(vs1[u]);
            d_h1h[(size_t)gw * 256 + 128 + c0 + u] = h1v;
            d_h1l[(size_t)gw * 256 + 128 + c0 + u] = __float2bfloat16(vs1[u] - __bfloat162float(h1v));
        }
    }
    float4* orow = (float4*)(out + (size_t)gw * 256);
    orow[lane] = a0; orow[lane + 32] = a1;
}

// -------- classification --------
__global__ void k_cls_scatter(const int* __restrict__ labels, const int* __restrict__ nidx) {
    int w = (blockIdx.x*256+threadIdx.x) >> 5, lane = threadIdx.x & 31;
    if (w >= NSEL) return;
    int lbl = labels[w];
    const float4* er = (const float4*)(d_emb + (size_t)nidx[w]*HIDD);
    float4* sr = (float4*)(d_sums + lbl*HIDD);
#pragma unroll
    for (int q = 0; q < 2; q++) {
        int f = lane + 32*q; float4 v = er[f];
        red4(&sr[f], v.x, v.y, v.z, v.w);
    }
    if (lane == 0) atomicAdd(&d_cnt[lbl], 1.f);
}
__global__ void k_proto() {
    int c = blockIdx.x, t = threadIdx.x;
    float cnt = d_cnt[c];
    float sm = d_sums[c*HIDD+t];
    float p = sm / fmaxf(cnt, 1.f);
    __shared__ float red[256];
    red[t] = p*p;
    __syncthreads();
    for (int s = 128; s > 0; s >>= 1) { if (t < s) red[t] += red[t+s]; __syncthreads(); }
    d_pn[c*HIDD+t] = p / (sqrtf(red[0]) + EPSF);
    d_sums[c*HIDD+t] = 0.f;
    if (t == 0) d_cnt[c] = 0.f;
}
__global__ void k_out(const int* __restrict__ nidx, float* __restrict__ out) {
    int w = (blockIdx.x*256+threadIdx.x) >> 5, lane = threadIdx.x & 31;
    if (w >= NSEL) return;
    const float* er = d_emb + (size_t)nidx[w]*HIDD;
    float v[8]; float ss = 0.f;
#pragma unroll
    for (int q = 0; q < 8; q++) { v[q] = er[lane+32*q]; ss += v[q]*v[q]; }
    ss = warp_sum(ss);
    float rn = 1.f / (sqrtf(ss) + EPSF);
#pragma unroll
    for (int c = 0; c < NCLS; c++) {
        float dp = 0.f;
#pragma unroll
        for (int q = 0; q < 8; q++) dp += v[q] * d_pn[c*HIDD + lane + 32*q];
        dp = warp_sum(dp);
        if (lane == 0) out[w*NCLS + c] = dp * rn * 5.0f;
    }
}

extern "C" void kernel_launch(void* const* d_in, const int* in_sizes, int n_in,
                              void* d_out, int out_size) {
    const float* x   = (const float*)d_in[0];
    const float* cw  = (const float*)d_in[1];
    const float* alp = (const float*)d_in[2];
    const float* ps  = (const float*)d_in[3];
    const float* st  = (const float*)d_in[4];
    const float* bal = (const float*)d_in[5];
    const float* W1  = (const float*)d_in[6];
    const float* W2  = (const float*)d_in[7];
    const int*   ei  = (const int*)d_in[8];
    const int*   lab = (const int*)d_in[9];
    const int*   nix = (const int*)d_in[10];
    float* out = (float*)d_out;
    const int* esrc = ei;
    const int* edst = ei + NE;

    cudaFuncSetAttribute(k_mma_sims, cudaFuncAttributeMaxDynamicSharedMemorySize, SIMS_SMEM);
    cudaFuncSetAttribute(k_gemm_bf16<0>, cudaFuncAttributeMaxDynamicSharedMemorySize, SIMS_SMEM);
    cudaFuncSetAttribute(k_gemm_bf16<1>, cudaFuncAttributeMaxDynamicSharedMemorySize, SIMS_SMEM);

    k_fea<<<NN*FIN/256, 256>>>(x, cw, ps, st, edst, W1, W2);
    k_scan<<<1, 256>>>();
    k_fill<<<NE/256, 256>>>(esrc, edst);
    k_agg_h<<<NN/8, 256>>>(bal);
    k_mma_sims<<<2080, 128, SIMS_SMEM>>>();
    k_topk<<<NN, 256>>>(alp);
    k_kcount<<<NN*KT/8, 256>>>();
    k_kscan<<<1, 256>>>();
    k_kfill<<<(NN*KT+255)/256, 256>>>();

    k_gemm_bf16<0><<<dim3(2, 64), 256, SIMS_SMEM>>>();
    k_spmm_gather<0><<<NN/8, 256>>>(alp);
    k_gemm_bf16<1><<<dim3(2, 64), 256, SIMS_SMEM>>>();
    k_spmm_gather<1><<<NN/8, 256>>>(alp);

    k_cls_scatter<<<NSEL/8, 256>>>(lab, nix);
    k_proto<<<NCLS, 256>>>();
    k_out<<<NSEL/8, 256>>>(nix, out);
}